// round 1
// baseline (speedup 1.0000x reference)
#include <cuda_runtime.h>
#include <math.h>

// Problem constants
#define BSZ 2048
#define XS  256
#define HS  512
#define RS  64
#define MS  128
#define KS  64
#define HQ  128   // H/4

// ---------------- device scratch (static, allocation-free) ----------------
__device__ float g_xcu[BSZ * 1024];          // [x, c, 0(128), l2n(u_t)]
__device__ float g_base[BSZ * HQ];
__device__ float g_kWk[MS * HQ];
__device__ float g_C0[33554432];             // (B*M, HQ) = 262144 x 128
__device__ float g_headraw[BSZ * MS];
__device__ float g_ri[BSZ * MS];
__device__ float g_r[BSZ * RS];
__device__ float g_concat0[BSZ * 832];       // [x, h, r]
__device__ float g_Z[BSZ * 1536];
__device__ float g_Gx[BSZ * HS];
__device__ float g_Gh[BSZ * HS];
__device__ float g_Gr[BSZ * HS];
__device__ float g_ab[BSZ * 2];
__device__ float g_xnh[BSZ * 768];           // [x, new_h]
__device__ float g_hw[BSZ * RS];

__device__ __forceinline__ float sigm(float v) { return 1.0f / (1.0f + expf(-v)); }
__device__ __forceinline__ float gumbelf(float u) {
    return -logf(1e-20f - logf(1e-20f + u));
}

// 128-thread block reductions (shared buffer of 128 floats)
__device__ __forceinline__ float blk_sum128(float v, float* red) {
    red[threadIdx.x] = v; __syncthreads();
    for (int s = 64; s > 0; s >>= 1) {
        if (threadIdx.x < s) red[threadIdx.x] += red[threadIdx.x + s];
        __syncthreads();
    }
    float r = red[0]; __syncthreads();
    return r;
}
__device__ __forceinline__ float blk_max128(float v, float* red) {
    red[threadIdx.x] = v; __syncthreads();
    for (int s = 64; s > 0; s >>= 1) {
        if (threadIdx.x < s) red[threadIdx.x] = fmaxf(red[threadIdx.x], red[threadIdx.x + s]);
        __syncthreads();
    }
    float r = red[0]; __syncthreads();
    return r;
}

// ---------------- generic fp32 GEMM: C = A(MxK) @ B(KxN) [+bias] ----------
// BM=BN=128, BK=8, 256 threads, 8x8 per thread. Requires M%128==0, N%128==0, K%8==0.
__global__ __launch_bounds__(256) void sgemm128(
    const float* __restrict__ A, int lda,
    const float* __restrict__ Bm, int ldb,
    float* __restrict__ C, int ldc,
    int Kk, const float* __restrict__ bias)
{
    __shared__ float As[8][128];
    __shared__ float Bs[8][128];
    const int tid = threadIdx.x;
    const int tx = tid & 15, ty = tid >> 4;
    const int row0 = blockIdx.y * 128;
    const int col0 = blockIdx.x * 128;
    const int arow = tid >> 1, acol = (tid & 1) * 4;
    const int brow = tid >> 5, bcol = (tid & 31) * 4;

    float acc[8][8];
#pragma unroll
    for (int i = 0; i < 8; i++)
#pragma unroll
        for (int j = 0; j < 8; j++) acc[i][j] = 0.0f;

    for (int k0 = 0; k0 < Kk; k0 += 8) {
        float4 a4 = *(const float4*)(A + (size_t)(row0 + arow) * lda + k0 + acol);
        float4 b4 = *(const float4*)(Bm + (size_t)(k0 + brow) * ldb + col0 + bcol);
        As[acol + 0][arow] = a4.x;
        As[acol + 1][arow] = a4.y;
        As[acol + 2][arow] = a4.z;
        As[acol + 3][arow] = a4.w;
        *(float4*)&Bs[brow][bcol] = b4;
        __syncthreads();
#pragma unroll
        for (int kk = 0; kk < 8; kk++) {
            float4 a0 = *(const float4*)&As[kk][ty * 8];
            float4 a1 = *(const float4*)&As[kk][ty * 8 + 4];
            float4 b0 = *(const float4*)&Bs[kk][tx * 8];
            float4 b1 = *(const float4*)&Bs[kk][tx * 8 + 4];
            float av[8] = {a0.x, a0.y, a0.z, a0.w, a1.x, a1.y, a1.z, a1.w};
            float bv[8] = {b0.x, b0.y, b0.z, b0.w, b1.x, b1.y, b1.z, b1.w};
#pragma unroll
            for (int i = 0; i < 8; i++)
#pragma unroll
                for (int j = 0; j < 8; j++) acc[i][j] += av[i] * bv[j];
        }
        __syncthreads();
    }

    float bv[8];
#pragma unroll
    for (int j = 0; j < 8; j++) bv[j] = bias ? bias[col0 + tx * 8 + j] : 0.0f;
#pragma unroll
    for (int i = 0; i < 8; i++) {
        float4 o0 = make_float4(acc[i][0] + bv[0], acc[i][1] + bv[1],
                                acc[i][2] + bv[2], acc[i][3] + bv[3]);
        float4 o1 = make_float4(acc[i][4] + bv[4], acc[i][5] + bv[5],
                                acc[i][6] + bv[6], acc[i][7] + bv[7]);
        float* crow = C + (size_t)(row0 + ty * 8 + i) * ldc + col0 + tx * 8;
        *(float4*)crow = o0;
        *(float4*)(crow + 4) = o1;
    }
}

// ---------------- stage kernels -------------------------------------------
// xcu = [x(256), c(512), zeros(128), l2n(u_t)(128)]  (zeros land on W_k/W_m rows)
__global__ void k_prep(const float* __restrict__ x, const float* __restrict__ c,
                       const float* __restrict__ u)
{
    __shared__ float red[128];
    int b = blockIdx.x, t = threadIdx.x;
    float uv = u[b * MS + t];
    float s = blk_sum128(uv * uv, red);
    float denom = fmaxf(sqrtf(s), 1e-12f);
    float* row = g_xcu + (size_t)b * 1024;
    for (int i = t; i < XS; i += 128) row[i] = x[(size_t)b * XS + i];
    for (int i = t; i < HS; i += 128) row[XS + i] = c[(size_t)b * HS + i];
    row[768 + t] = 0.0f;
    row[896 + t] = uv / denom;
}

// kWk[m, k] = keys[m, :] @ W_fc[768:832, k]
__global__ void k_kwk(const float* __restrict__ keys, const float* __restrict__ W_fc)
{
    int m = blockIdx.x, t = threadIdx.x;
    float acc = 0.0f;
#pragma unroll 8
    for (int r = 0; r < KS; r++)
        acc += keys[m * KS + r] * W_fc[(768 + r) * HQ + t];
    g_kWk[m * HQ + t] = acc;
}

// head[b,m] = sum_k tanh(C0[bm,k] + base[b,k] + kWk[m,k]) * vec_a[k]
__global__ void k_head(const float* __restrict__ vec_a)
{
    int row = blockIdx.x * 4 + (threadIdx.x >> 5);
    int lane = threadIdx.x & 31;
    int b = row >> 7, m = row & 127;
    float acc = 0.0f;
#pragma unroll
    for (int kq = 0; kq < 4; kq++) {
        int k = lane + kq * 32;
        float v = g_C0[(size_t)row * HQ + k] + g_base[b * HQ + k] + g_kWk[m * HQ + k];
        acc += tanhf(v) * vec_a[k];
    }
#pragma unroll
    for (int off = 16; off; off >>= 1) acc += __shfl_down_sync(0xffffffffu, acc, off);
    if (lane == 0) g_headraw[row] = acc;
}

// l2n(head - 100*prev) -> gumbel-softmax -> hard straight-through -> ri -> r -> concat0
__global__ void k_select(const float* __restrict__ x, const float* __restrict__ h,
                         const float* __restrict__ hmem, const float* __restrict__ prev,
                         const float* __restrict__ noise_sm, float* __restrict__ out)
{
    __shared__ float red[128];
    __shared__ float ri_s[128];
    __shared__ float r_s[64];
    int b = blockIdx.x, t = threadIdx.x;

    float hv = g_headraw[b * MS + t] - prev[b * MS + t] * 100.0f;
    float s = blk_sum128(hv * hv, red);
    float hn = hv / fmaxf(sqrtf(s), 1e-12f);
    float z = (hn + gumbelf(noise_sm[b * MS + t])) * 1.0f;  // TAU = 1
    float zmax = blk_max128(z, red);
    float e = expf(z - zmax);
    float es = blk_sum128(e, red);
    float y = e / es;
    float ymax = blk_max128(y, red);
    float hard = (y == ymax) ? 1.0f : 0.0f;
    float ri = (hard - y) + y;
    g_ri[b * MS + t] = ri;
    ri_s[t] = ri;
    __syncthreads();

    if (t < RS) {
        float acc = 0.0f;
        const float* hm = hmem + ((size_t)b * MS) * RS + t;
#pragma unroll 8
        for (int m = 0; m < MS; m++) acc += ri_s[m] * hm[(size_t)m * RS];
        r_s[t] = acc;
        g_r[b * RS + t] = acc;
        out[(size_t)b * 576 + HS + t] = acc;
    }
    __syncthreads();

    float* crow = g_concat0 + (size_t)b * 832;
    for (int i = t; i < XS; i += 128) crow[i] = x[(size_t)b * XS + i];
    for (int i = t; i < HS; i += 128) crow[XS + i] = h[(size_t)b * HS + i];
    if (t < RS) crow[768 + t] = r_s[t];
}

// ab = sigmoid((concat0 @ W_full1 + bias1 + gumbel(noise_sig)) * SIG_TAU)
__global__ void k_ab(const float* __restrict__ W_full1, const float* __restrict__ bias1,
                     const float* __restrict__ noise_sig)
{
    __shared__ float red[128];
    int b = blockIdx.x, t = threadIdx.x;
    float s0 = 0.0f, s1 = 0.0f;
    const float* crow = g_concat0 + (size_t)b * 832;
    for (int k = t; k < 832; k += 128) {
        float cv = crow[k];
        s0 += cv * W_full1[k * 2 + 0];
        s1 += cv * W_full1[k * 2 + 1];
    }
    float S0 = blk_sum128(s0, red);
    float S1 = blk_sum128(s1, red);
    if (t < 2) {
        float sv = (t == 0 ? S0 : S1) + bias1[t];
        float val = (sv + gumbelf(noise_sig[b * 2 + t])) * (10.0f / 3.0f);
        g_ab[b * 2 + t] = sigm(val);
    }
}

// LSTM-ish epilogue: new_c, new_h; write new_h to out + build xnh = [x, new_h]
__global__ void k_epi(const float* __restrict__ x, const float* __restrict__ c,
                      const float* __restrict__ bias2, float* __restrict__ out)
{
    int b = blockIdx.x, t = threadIdx.x;
    float al = g_ab[b * 2 + 0];
    float be = g_ab[b * 2 + 1];
    for (int j = t; j < HS; j += 128) {
        size_t bj = (size_t)b * HS + j;
        float pre = g_Gx[bj] + al * g_Gh[bj] + be * g_Gr[bj] + bias2[j];
        float nc = tanhf(pre);
        float zi = g_Z[(size_t)b * 1536 + j];
        float zf = g_Z[(size_t)b * 1536 + 512 + j];
        float zo = g_Z[(size_t)b * 1536 + 1024 + j];
        float cc = c[bj];
        float ncv = cc * sigm(zf + 1.0f) + sigm(zi) * nc;   // F_BIAS = 1
        float nh = tanhf(ncv) * sigm(zo);
        out[(size_t)b * 576 + j] = nh;
        g_xnh[(size_t)b * 768 + XS + j] = nh;
    }
    for (int i = t; i < XS; i += 128) g_xnh[(size_t)b * 768 + i] = x[(size_t)b * XS + i];
}

// h_w = [x, new_h] @ W_fc1 + b_fc1   (K=768, N=64)
__global__ void k_hw(const float* __restrict__ W_fc1, const float* __restrict__ b_fc1)
{
    __shared__ float rowsh[768];
    int b = blockIdx.x, t = threadIdx.x;  // 64 threads
    for (int i = t; i < 768; i += 64) rowsh[i] = g_xnh[(size_t)b * 768 + i];
    __syncthreads();
    float acc = b_fc1[t];
#pragma unroll 8
    for (int k = 0; k < 768; k++) acc += rowsh[k] * W_fc1[k * RS + t];
    g_hw[b * RS + t] = acc;
}

// new_hmem = h_w * wi + hmem * (1 - wi),  wi = ri  (memcnt == M in this setup)
__global__ void k_hmem(const float* __restrict__ hmem, float* __restrict__ out)
{
    int idx = blockIdx.x * blockDim.x + threadIdx.x;      // float4 index over B*M*16
    int q = idx & 15;
    int m = (idx >> 4) & 127;
    int b = idx >> 11;
    float w = g_ri[b * MS + m];
    float om = 1.0f - w;
    float4 hv = ((const float4*)hmem)[(size_t)idx];
    float4 hw = ((const float4*)g_hw)[b * 16 + q];
    float4 o;
    o.x = hw.x * w + hv.x * om;
    o.y = hw.y * w + hv.y * om;
    o.z = hw.z * w + hv.z * om;
    o.w = hw.w * w + hv.w * om;
    ((float4*)out)[(size_t)(BSZ * 576 / 4) + idx] = o;
}

// ---------------- launch --------------------------------------------------
extern "C" void kernel_launch(void* const* d_in, const int* in_sizes, int n_in,
                              void* d_out, int out_size)
{
    const float* x        = (const float*)d_in[0];
    const float* h        = (const float*)d_in[1];
    const float* c        = (const float*)d_in[2];
    const float* hmem     = (const float*)d_in[3];
    const float* u_t      = (const float*)d_in[4];
    const float* prev     = (const float*)d_in[5];
    const float* W_full   = (const float*)d_in[6];
    const float* bias     = (const float*)d_in[7];
    const float* W_full1  = (const float*)d_in[8];
    const float* bias1    = (const float*)d_in[9];
    const float* W_full2  = (const float*)d_in[10];
    const float* bias2    = (const float*)d_in[11];
    const float* keys     = (const float*)d_in[12];
    const float* vec_a    = (const float*)d_in[13];
    const float* W_fc     = (const float*)d_in[14];
    const float* b_fc     = (const float*)d_in[15];
    const float* W_fc1    = (const float*)d_in[16];
    const float* b_fc1    = (const float*)d_in[17];
    const float* noise_sm = (const float*)d_in[18];
    const float* noise_sig= (const float*)d_in[19];
    float* out = (float*)d_out;

    float *p_xcu, *p_base, *p_C0, *p_concat0, *p_Z, *p_Gx, *p_Gh, *p_Gr;
    cudaGetSymbolAddress((void**)&p_xcu,     g_xcu);
    cudaGetSymbolAddress((void**)&p_base,    g_base);
    cudaGetSymbolAddress((void**)&p_C0,      g_C0);
    cudaGetSymbolAddress((void**)&p_concat0, g_concat0);
    cudaGetSymbolAddress((void**)&p_Z,       g_Z);
    cudaGetSymbolAddress((void**)&p_Gx,      g_Gx);
    cudaGetSymbolAddress((void**)&p_Gh,      g_Gh);
    cudaGetSymbolAddress((void**)&p_Gr,      g_Gr);

    // 1) xcu build + keys@W_k
    k_prep<<<BSZ, 128>>>(x, c, u_t);
    k_kwk<<<MS, HQ>>>(keys, W_fc);

    // 2) base = xcu @ W_fc + b_fc   (K=1024 with zero-padded W_k/W_m rows)
    sgemm128<<<dim3(1, BSZ / 128), 256>>>(p_xcu, 1024, W_fc, HQ, p_base, HQ, 1024, b_fc);

    // 3) C0 = hmem_flat(262144 x 64) @ W_m(64 x 128)
    sgemm128<<<dim3(1, (BSZ * MS) / 128), 256>>>(hmem, RS, W_fc + 832 * HQ, HQ,
                                                 p_C0, HQ, RS, nullptr);

    // 4) head reduce; 5) gumbel-softmax select + r + concat0
    k_head<<<(BSZ * MS) / 4, 128>>>(vec_a);
    k_select<<<BSZ, 128>>>(x, h, hmem, prev, noise_sm, out);

    // 6) big GEMMs off concat0
    sgemm128<<<dim3(1536 / 128, BSZ / 128), 256>>>(p_concat0, 832, W_full, 1536,
                                                   p_Z, 1536, 832, bias);
    sgemm128<<<dim3(HS / 128, BSZ / 128), 256>>>(p_concat0, 832, W_full2, HS,
                                                 p_Gx, HS, XS, nullptr);
    sgemm128<<<dim3(HS / 128, BSZ / 128), 256>>>(p_concat0 + XS, 832, W_full2 + XS * HS, HS,
                                                 p_Gh, HS, HS, nullptr);
    sgemm128<<<dim3(HS / 128, BSZ / 128), 256>>>(p_concat0 + 768, 832, W_full2 + 768 * HS, HS,
                                                 p_Gr, HS, RS, nullptr);

    // 7) alpha/beta; 8) cell epilogue
    k_ab<<<BSZ, 128>>>(W_full1, bias1, noise_sig);
    k_epi<<<BSZ, 128>>>(x, c, bias2, out);

    // 9) h_w; 10) hmem update into output
    k_hw<<<BSZ, 64>>>(W_fc1, b_fc1);
    k_hmem<<<(BSZ * MS * 16) / 256, 256>>>(hmem, out);
}

// round 3
// speedup vs baseline: 1.4027x; 1.4027x over previous
#include <cuda_runtime.h>
#include <math.h>

#define BSZ 2048
#define XS  256
#define HS  512
#define RS  64
#define MS  128
#define KS  64
#define HQ  128   // H/4

// ---------------- device scratch ----------------
__device__ float g_xcu[BSZ * 1024];     // [x, c, 0(128), l2n(u_t)]
__device__ float g_base[BSZ * HQ];
__device__ float g_kWk[MS * HQ];
__device__ float g_ri[BSZ * MS];
__device__ float g_r[BSZ * RS];
__device__ float g_Z[BSZ * 1536];
__device__ float g_G[BSZ * HS];
__device__ float g_ab[BSZ * 2];
__device__ float g_nh[BSZ * HS];
__device__ float g_hw[BSZ * RS];

__device__ __forceinline__ float sigm(float v) { return 1.0f / (1.0f + expf(-v)); }
__device__ __forceinline__ float gumbelf(float u) {
    return -logf(1e-20f - logf(1e-20f + u));
}

// ---------------- double-buffered fp32 GEMM core ----------------
// 128x128 tile, BK=8, 256 threads, 8x8/thread, 1 sync per k-tile.
__device__ __forceinline__ void gemm_inner(const float (*As)[128], const float (*Bs)[128],
                                           float acc[8][8], int tx, int ty)
{
#pragma unroll
    for (int kk = 0; kk < 8; kk++) {
        float4 a0 = *(const float4*)&As[kk][ty * 8];
        float4 a1 = *(const float4*)&As[kk][ty * 8 + 4];
        float4 b0 = *(const float4*)&Bs[kk][tx * 8];
        float4 b1 = *(const float4*)&Bs[kk][tx * 8 + 4];
        float av[8] = {a0.x, a0.y, a0.z, a0.w, a1.x, a1.y, a1.z, a1.w};
        float bv[8] = {b0.x, b0.y, b0.z, b0.w, b1.x, b1.y, b1.z, b1.w};
#pragma unroll
        for (int i = 0; i < 8; i++)
#pragma unroll
            for (int j = 0; j < 8; j++) acc[i][j] += av[i] * bv[j];
    }
}

// Plain GEMM (for base = xcu @ W_fc)
__global__ __launch_bounds__(256, 2) void gemm_plain(
    const float* __restrict__ A, int lda,
    const float* __restrict__ B, int ldb,
    const float* __restrict__ bias,
    float* __restrict__ C, int ldc, int Kk)
{
    __shared__ float As[2][8][128];
    __shared__ float Bs[2][8][128];
    const int tid = threadIdx.x;
    const int tx = tid & 15, ty = tid >> 4;
    const int row0 = blockIdx.y * 128, col0 = blockIdx.x * 128;
    const int arow = tid >> 1, acol = (tid & 1) * 4;
    const int brow = tid >> 5, bcol = (tid & 31) * 4;

    const float* Aptr = A + (size_t)(row0 + arow) * lda + acol;
    const float* Bptr = B + (size_t)brow * ldb + col0 + bcol;

    float acc[8][8];
#pragma unroll
    for (int i = 0; i < 8; i++)
#pragma unroll
        for (int j = 0; j < 8; j++) acc[i][j] = 0.0f;

    float4 ra = *(const float4*)Aptr;
    float4 rb = *(const float4*)Bptr;
    As[0][acol + 0][arow] = ra.x; As[0][acol + 1][arow] = ra.y;
    As[0][acol + 2][arow] = ra.z; As[0][acol + 3][arow] = ra.w;
    *(float4*)&Bs[0][brow][bcol] = rb;
    __syncthreads();

    const int nt = Kk / 8;
    for (int i = 0; i < nt; i++) {
        int cur = i & 1;
        if (i + 1 < nt) {
            ra = *(const float4*)(Aptr + (i + 1) * 8);
            rb = *(const float4*)(Bptr + (size_t)(i + 1) * 8 * ldb);
        }
        gemm_inner(As[cur], Bs[cur], acc, tx, ty);
        if (i + 1 < nt) {
            int nxt = cur ^ 1;
            As[nxt][acol + 0][arow] = ra.x; As[nxt][acol + 1][arow] = ra.y;
            As[nxt][acol + 2][arow] = ra.z; As[nxt][acol + 3][arow] = ra.w;
            *(float4*)&Bs[nxt][brow][bcol] = rb;
            __syncthreads();
        }
    }

    float bv[8];
#pragma unroll
    for (int j = 0; j < 8; j++) bv[j] = bias ? bias[col0 + tx * 8 + j] : 0.0f;
#pragma unroll
    for (int i = 0; i < 8; i++) {
        float* crow = C + (size_t)(row0 + ty * 8 + i) * ldc + col0 + tx * 8;
        float4 o0 = make_float4(acc[i][0] + bv[0], acc[i][1] + bv[1],
                                acc[i][2] + bv[2], acc[i][3] + bv[3]);
        float4 o1 = make_float4(acc[i][4] + bv[4], acc[i][5] + bv[5],
                                acc[i][6] + bv[6], acc[i][7] + bv[7]);
        *(float4*)crow = o0; *(float4*)(crow + 4) = o1;
    }
}

// Combined Z + G GEMM. A gathered from [x | h | r] (K=832), per-row scale
// [1, alpha, beta] applied for G blocks (blockIdx.x >= 12).
__global__ __launch_bounds__(256, 2) void gemm_big(
    const float* __restrict__ x, const float* __restrict__ h,
    const float* __restrict__ r, const float* __restrict__ ab,
    const float* __restrict__ W_full, const float* __restrict__ bias,
    const float* __restrict__ W_full2,
    float* __restrict__ Zout, float* __restrict__ Gout)
{
    __shared__ float As[2][8][128];
    __shared__ float Bs[2][8][128];
    const int tid = threadIdx.x;
    const int tx = tid & 15, ty = tid >> 4;
    const int row0 = blockIdx.y * 128;
    const bool isG = blockIdx.x >= 12;
    const int col0 = (isG ? blockIdx.x - 12 : blockIdx.x) * 128;
    const int ldb = isG ? 512 : 1536;
    const float* Bsrc = isG ? W_full2 : W_full;
    const int arow = tid >> 1, acol = (tid & 1) * 4;
    const int brow = tid >> 5, bcol = (tid & 31) * 4;

    const int bidx = row0 + arow;   // global batch row this thread loads A for
    float alpha = 1.0f, beta = 1.0f;
    if (isG) { alpha = ab[bidx * 2]; beta = ab[bidx * 2 + 1]; }

    const float* Bptr = Bsrc + (size_t)brow * ldb + col0 + bcol;

    float acc[8][8];
#pragma unroll
    for (int i = 0; i < 8; i++)
#pragma unroll
        for (int j = 0; j < 8; j++) acc[i][j] = 0.0f;

    // gather loader: col c -> x / h / r segment, with scale
    auto loadA = [&](int c) -> float4 {
        float4 v; float s;
        if (c < 256)      { v = *(const float4*)(x + (size_t)bidx * 256 + c); s = 1.0f; }
        else if (c < 768) { v = *(const float4*)(h + (size_t)bidx * 512 + (c - 256)); s = alpha; }
        else              { v = *(const float4*)(r + (size_t)bidx * 64 + (c - 768)); s = beta; }
        v.x *= s; v.y *= s; v.z *= s; v.w *= s;
        return v;
    };

    float4 ra = loadA(acol);
    float4 rb = *(const float4*)Bptr;
    As[0][acol + 0][arow] = ra.x; As[0][acol + 1][arow] = ra.y;
    As[0][acol + 2][arow] = ra.z; As[0][acol + 3][arow] = ra.w;
    *(float4*)&Bs[0][brow][bcol] = rb;
    __syncthreads();

    const int nt = 832 / 8;   // 104
    for (int i = 0; i < nt; i++) {
        int cur = i & 1;
        if (i + 1 < nt) {
            ra = loadA((i + 1) * 8 + acol);
            rb = *(const float4*)(Bptr + (size_t)(i + 1) * 8 * ldb);
        }
        gemm_inner(As[cur], Bs[cur], acc, tx, ty);
        if (i + 1 < nt) {
            int nxt = cur ^ 1;
            As[nxt][acol + 0][arow] = ra.x; As[nxt][acol + 1][arow] = ra.y;
            As[nxt][acol + 2][arow] = ra.z; As[nxt][acol + 3][arow] = ra.w;
            *(float4*)&Bs[nxt][brow][bcol] = rb;
            __syncthreads();
        }
    }

    float bv[8];
#pragma unroll
    for (int j = 0; j < 8; j++) bv[j] = isG ? 0.0f : bias[col0 + tx * 8 + j];
    float* Cbase = isG ? Gout : Zout;
    const int ldc = isG ? 512 : 1536;
#pragma unroll
    for (int i = 0; i < 8; i++) {
        float* crow = Cbase + (size_t)(row0 + ty * 8 + i) * ldc + col0 + tx * 8;
        float4 o0 = make_float4(acc[i][0] + bv[0], acc[i][1] + bv[1],
                                acc[i][2] + bv[2], acc[i][3] + bv[3]);
        float4 o1 = make_float4(acc[i][4] + bv[4], acc[i][5] + bv[5],
                                acc[i][6] + bv[6], acc[i][7] + bv[7]);
        *(float4*)crow = o0; *(float4*)(crow + 4) = o1;
    }
}

// ---------------- fused head + selection + alpha/beta ----------------
struct HSmem {
    float hm[128][65];      // hmem[b], padded
    float wm[64][128];      // W_m
    float part[128][17];    // head partials across tx
    float red[256];
    float ri[128];
    float rs[64];
};

__global__ __launch_bounds__(256, 2) void k_headsel(
    const float* __restrict__ x, const float* __restrict__ h,
    const float* __restrict__ hmem, const float* __restrict__ prev,
    const float* __restrict__ noise_sm, const float* __restrict__ noise_sig,
    const float* __restrict__ W_fc, const float* __restrict__ vec_a,
    const float* __restrict__ W_full1, const float* __restrict__ bias1,
    float* __restrict__ out)
{
    extern __shared__ char smem_raw[];
    HSmem& S = *(HSmem*)smem_raw;
    const int b = blockIdx.x;
    const int t = threadIdx.x;
    const int tx = t & 15, ty = t >> 4;

    // load hmem[b] (128x64) into padded smem
    {
        const float4* src = (const float4*)(hmem + (size_t)b * (MS * RS));
#pragma unroll
        for (int i = 0; i < 8; i++) {
            int idx = t + i * 256;           // 0..2047
            float4 v = src[idx];
            int m = idx >> 4;
            int rr = (idx & 15) * 4;
            S.hm[m][rr] = v.x; S.hm[m][rr + 1] = v.y;
            S.hm[m][rr + 2] = v.z; S.hm[m][rr + 3] = v.w;
        }
    }
    // load W_m (rows 832..895 of W_fc), 64x128
    {
        const float4* wsrc = (const float4*)(W_fc + 832 * HQ);
#pragma unroll
        for (int i = 0; i < 8; i++) {
            int idx = t + i * 256;           // 0..2047
            float4 v = wsrc[idx];
            int rr = idx >> 5;
            int kk = (idx & 31) * 4;
            *(float4*)&S.wm[rr][kk] = v;
        }
    }
    __syncthreads();

    // GEMM: acc[i][j] = sum_r hm[ty*8+i][r] * wm[r][tx*8+j]
    float acc[8][8];
#pragma unroll
    for (int i = 0; i < 8; i++)
#pragma unroll
        for (int j = 0; j < 8; j++) acc[i][j] = 0.0f;
#pragma unroll 4
    for (int rr = 0; rr < 64; rr++) {
        float av[8];
#pragma unroll
        for (int i = 0; i < 8; i++) av[i] = S.hm[ty * 8 + i][rr];
        float4 b0 = *(const float4*)&S.wm[rr][tx * 8];
        float4 b1 = *(const float4*)&S.wm[rr][tx * 8 + 4];
        float bvv[8] = {b0.x, b0.y, b0.z, b0.w, b1.x, b1.y, b1.z, b1.w};
#pragma unroll
        for (int i = 0; i < 8; i++)
#pragma unroll
            for (int j = 0; j < 8; j++) acc[i][j] += av[i] * bvv[j];
    }

    // epilogue: tanh(acc + base + kWk) * vec_a, reduce over k
    {
        float4 bs0 = *(const float4*)(g_base + b * HQ + tx * 8);
        float4 bs1 = *(const float4*)(g_base + b * HQ + tx * 8 + 4);
        float4 va0 = *(const float4*)(vec_a + tx * 8);
        float4 va1 = *(const float4*)(vec_a + tx * 8 + 4);
        float bj[8] = {bs0.x, bs0.y, bs0.z, bs0.w, bs1.x, bs1.y, bs1.z, bs1.w};
        float vj[8] = {va0.x, va0.y, va0.z, va0.w, va1.x, va1.y, va1.z, va1.w};
#pragma unroll
        for (int i = 0; i < 8; i++) {
            int m = ty * 8 + i;
            float4 kw0 = *(const float4*)(g_kWk + m * HQ + tx * 8);
            float4 kw1 = *(const float4*)(g_kWk + m * HQ + tx * 8 + 4);
            float kw[8] = {kw0.x, kw0.y, kw0.z, kw0.w, kw1.x, kw1.y, kw1.z, kw1.w};
            float hp = 0.0f;
#pragma unroll
            for (int j = 0; j < 8; j++)
                hp += tanhf(acc[i][j] + bj[j] + kw[j]) * vj[j];
            S.part[m][tx] = hp;
        }
    }
    __syncthreads();

    // head[m], selection (threads t<128 own m=t; all threads join reductions)
    float hv = 0.0f;
    if (t < MS) {
#pragma unroll
        for (int q = 0; q < 16; q++) hv += S.part[t][q];
        hv -= prev[(size_t)b * MS + t] * 100.0f;
    }
    // l2 normalize
    {
        float v = (t < MS) ? hv * hv : 0.0f;
        S.red[t] = v; __syncthreads();
        for (int s = 128; s > 0; s >>= 1) {
            if (t < s) S.red[t] += S.red[t + s];
            __syncthreads();
        }
        float nrm = fmaxf(sqrtf(S.red[0]), 1e-12f);
        __syncthreads();
        if (t < MS) hv /= nrm;
    }
    float z = (t < MS) ? hv + gumbelf(noise_sm[(size_t)b * MS + t]) : -INFINITY;
    // softmax
    float y = 0.0f;
    {
        S.red[t] = z; __syncthreads();
        for (int s = 128; s > 0; s >>= 1) {
            if (t < s) S.red[t] = fmaxf(S.red[t], S.red[t + s]);
            __syncthreads();
        }
        float zmax = S.red[0]; __syncthreads();
        float e = (t < MS) ? expf(z - zmax) : 0.0f;
        S.red[t] = e; __syncthreads();
        for (int s = 128; s > 0; s >>= 1) {
            if (t < s) S.red[t] += S.red[t + s];
            __syncthreads();
        }
        float es = S.red[0]; __syncthreads();
        y = e / es;
        S.red[t] = (t < MS) ? y : 0.0f; __syncthreads();
        for (int s = 128; s > 0; s >>= 1) {
            if (t < s) S.red[t] = fmaxf(S.red[t], S.red[t + s]);
            __syncthreads();
        }
        float ymax = S.red[0]; __syncthreads();
        if (t < MS) {
            float hard = (y == ymax) ? 1.0f : 0.0f;
            float ri = (hard - y) + y;      // exactly 0 off-support
            S.ri[t] = ri;
            g_ri[(size_t)b * MS + t] = ri;
        }
    }
    __syncthreads();

    // r = sum_m ri[m] * hmem[b][m][:]  (from smem; off-support terms exact 0)
    if (t < RS) {
        float a = 0.0f;
#pragma unroll 8
        for (int m = 0; m < MS; m++) a += S.ri[m] * S.hm[m][t];
        S.rs[t] = a;
        g_r[(size_t)b * RS + t] = a;
        out[(size_t)b * 576 + HS + t] = a;
    }
    __syncthreads();

    // alpha/beta logits: [x,h,r] @ W_full1
    {
        float s0 = 0.0f, s1 = 0.0f;
        for (int cI = t; cI < 832; cI += 256) {
            float v;
            if (cI < 256)      v = x[(size_t)b * XS + cI];
            else if (cI < 768) v = h[(size_t)b * HS + (cI - 256)];
            else               v = S.rs[cI - 768];
            s0 += v * W_full1[cI * 2 + 0];
            s1 += v * W_full1[cI * 2 + 1];
        }
        S.red[t] = s0; __syncthreads();
        for (int s = 128; s > 0; s >>= 1) {
            if (t < s) S.red[t] += S.red[t + s];
            __syncthreads();
        }
        float S0 = S.red[0]; __syncthreads();
        S.red[t] = s1; __syncthreads();
        for (int s = 128; s > 0; s >>= 1) {
            if (t < s) S.red[t] += S.red[t + s];
            __syncthreads();
        }
        float S1 = S.red[0];
        if (t == 0)
            g_ab[b * 2 + 0] = sigm((S0 + bias1[0] + gumbelf(noise_sig[b * 2 + 0])) * (10.0f / 3.0f));
        if (t == 1)
            g_ab[b * 2 + 1] = sigm((S1 + bias1[1] + gumbelf(noise_sig[b * 2 + 1])) * (10.0f / 3.0f));
    }
}

// ---------------- small kernels ----------------
__global__ void k_prep(const float* __restrict__ x, const float* __restrict__ c,
                       const float* __restrict__ u)
{
    __shared__ float red[128];
    int b = blockIdx.x, t = threadIdx.x;
    float uv = u[b * MS + t];
    red[t] = uv * uv; __syncthreads();
    for (int s = 64; s > 0; s >>= 1) {
        if (t < s) red[t] += red[t + s];
        __syncthreads();
    }
    float denom = fmaxf(sqrtf(red[0]), 1e-12f);
    float* row = g_xcu + (size_t)b * 1024;
    for (int i = t; i < XS; i += 128) row[i] = x[(size_t)b * XS + i];
    for (int i = t; i < HS; i += 128) row[XS + i] = c[(size_t)b * HS + i];
    row[768 + t] = 0.0f;
    row[896 + t] = uv / denom;
}

__global__ void k_kwk(const float* __restrict__ keys, const float* __restrict__ W_fc)
{
    int m = blockIdx.x, t = threadIdx.x;
    float a = 0.0f;
#pragma unroll 8
    for (int r = 0; r < KS; r++)
        a += keys[m * KS + r] * W_fc[(768 + r) * HQ + t];
    g_kWk[m * HQ + t] = a;
}

__global__ void k_epi(const float* __restrict__ c, const float* __restrict__ bias2,
                      float* __restrict__ out)
{
    int b = blockIdx.x, t = threadIdx.x;   // 256 threads
    for (int j = t; j < HS; j += 256) {
        size_t bj = (size_t)b * HS + j;
        float pre = g_G[bj] + bias2[j];
        float nc0 = tanhf(pre);
        float zi = g_Z[(size_t)b * 1536 + j];
        float zf = g_Z[(size_t)b * 1536 + 512 + j];
        float zo = g_Z[(size_t)b * 1536 + 1024 + j];
        float cc = c[bj];
        float ncv = cc * sigm(zf + 1.0f) + sigm(zi) * nc0;
        float nh = tanhf(ncv) * sigm(zo);
        out[(size_t)b * 576 + j] = nh;
        g_nh[bj] = nh;
    }
}

// h_w = [x, new_h] @ W_fc1 + b_fc1 ; tiled over 16 batch rows per block
// Asb stride 68 floats: keeps every row 16B-aligned for float4 stores
// (stride 65 caused the R2 misaligned-address trap).
__global__ __launch_bounds__(256) void k_hw(
    const float* __restrict__ x, const float* __restrict__ W_fc1,
    const float* __restrict__ b_fc1)
{
    __shared__ float Ws[64][64];
    __shared__ float Asb[16][68];
    const int b0 = blockIdx.x * 16;
    const int t = threadIdx.x;
    const int n = t & 63, bl = t >> 6;   // bl 0..3, 4 rows each
    float acc[4] = {0.0f, 0.0f, 0.0f, 0.0f};

    for (int k0 = 0; k0 < 768; k0 += 64) {
        // W tile 64x64
#pragma unroll
        for (int i = 0; i < 4; i++) {
            int idx = t + i * 256;          // 0..1023 float4s
            int row = idx >> 4, c4 = (idx & 15) * 4;
            *(float4*)&Ws[row][c4] = *(const float4*)(W_fc1 + (size_t)(k0 + row) * RS + c4);
        }
        // A tile 16x64 gathered from x / new_h
        {
            int idx = t;                    // 256 float4s
            int row = idx >> 4, c4 = (idx & 15) * 4;
            int gb = b0 + row, gk = k0 + c4;
            float4 v;
            if (gk < 256) v = *(const float4*)(x + (size_t)gb * XS + gk);
            else          v = *(const float4*)(g_nh + (size_t)gb * HS + (gk - 256));
            *(float4*)&Asb[row][c4] = v;
        }
        __syncthreads();
#pragma unroll 16
        for (int kk = 0; kk < 64; kk++) {
            float w = Ws[kk][n];
#pragma unroll
            for (int i = 0; i < 4; i++) acc[i] += Asb[bl * 4 + i][kk] * w;
        }
        __syncthreads();
    }
    float bb = b_fc1[n];
#pragma unroll
    for (int i = 0; i < 4; i++)
        g_hw[(size_t)(b0 + bl * 4 + i) * RS + n] = acc[i] + bb;
}

// new_hmem: blend (ri exactly 0 off-support -> bitwise copy there)
__global__ void k_hmem(const float* __restrict__ hmem, float* __restrict__ out)
{
    int idx = blockIdx.x * blockDim.x + threadIdx.x;   // float4 idx over B*M*16
    int q = idx & 15;
    int m = (idx >> 4) & 127;
    int b = idx >> 11;
    float w = g_ri[b * MS + m];
    float4 hv = ((const float4*)hmem)[(size_t)idx];
    float4 o = hv;
    if (w != 0.0f) {
        float om = 1.0f - w;
        float4 hw = ((const float4*)g_hw)[b * 16 + q];
        o.x = hw.x * w + hv.x * om;
        o.y = hw.y * w + hv.y * om;
        o.z = hw.z * w + hv.z * om;
        o.w = hw.w * w + hv.w * om;
    }
    ((float4*)out)[(size_t)(BSZ * 576 / 4) + idx] = o;
}

// ---------------- launch ----------------
extern "C" void kernel_launch(void* const* d_in, const int* in_sizes, int n_in,
                              void* d_out, int out_size)
{
    const float* x        = (const float*)d_in[0];
    const float* h        = (const float*)d_in[1];
    const float* c        = (const float*)d_in[2];
    const float* hmem     = (const float*)d_in[3];
    const float* u_t      = (const float*)d_in[4];
    const float* prev     = (const float*)d_in[5];
    const float* W_full   = (const float*)d_in[6];
    const float* bias     = (const float*)d_in[7];
    const float* W_full1  = (const float*)d_in[8];
    const float* bias1    = (const float*)d_in[9];
    const float* W_full2  = (const float*)d_in[10];
    const float* bias2    = (const float*)d_in[11];
    const float* keys     = (const float*)d_in[12];
    const float* vec_a    = (const float*)d_in[13];
    const float* W_fc     = (const float*)d_in[14];
    const float* b_fc     = (const float*)d_in[15];
    const float* W_fc1    = (const float*)d_in[16];
    const float* b_fc1    = (const float*)d_in[17];
    const float* noise_sm = (const float*)d_in[18];
    const float* noise_sig= (const float*)d_in[19];
    float* out = (float*)d_out;

    float *p_xcu, *p_base, *p_r, *p_ab, *p_Z, *p_G;
    cudaGetSymbolAddress((void**)&p_xcu,  g_xcu);
    cudaGetSymbolAddress((void**)&p_base, g_base);
    cudaGetSymbolAddress((void**)&p_r,    g_r);
    cudaGetSymbolAddress((void**)&p_ab,   g_ab);
    cudaGetSymbolAddress((void**)&p_Z,    g_Z);
    cudaGetSymbolAddress((void**)&p_G,    g_G);

    static bool attr_set = false;
    if (!attr_set) {
        cudaFuncSetAttribute(k_headsel, cudaFuncAttributeMaxDynamicSharedMemorySize,
                             (int)sizeof(HSmem));
        attr_set = true;
    }

    // 1) xcu + keys@W_k
    k_prep<<<BSZ, 128>>>(x, c, u_t);
    k_kwk<<<MS, HQ>>>(keys, W_fc);

    // 2) base = xcu @ W_fc + b_fc  (K=1024, zero-padded W_k/W_m rows)
    gemm_plain<<<dim3(1, BSZ / 128), 256>>>(p_xcu, 1024, W_fc, HQ, b_fc, p_base, HQ, 1024);

    // 3) fused head + selection + alpha/beta
    k_headsel<<<BSZ, 256, sizeof(HSmem)>>>(x, h, hmem, prev, noise_sm, noise_sig,
                                           W_fc, vec_a, W_full1, bias1, out);

    // 4) combined Z + scaled-G GEMM (A gathered from x/h/r)
    gemm_big<<<dim3(16, BSZ / 128), 256>>>(x, h, p_r, p_ab, W_full, bias, W_full2,
                                           p_Z, p_G);

    // 5) cell epilogue -> new_h
    k_epi<<<BSZ, 256>>>(c, bias2, out);

    // 6) h_w ; 7) hmem blend-copy
    k_hw<<<BSZ / 16, 256>>>(x, W_fc1, b_fc1);
    k_hmem<<<(BSZ * MS * 16) / 256, 256>>>(hmem, out);
}

// round 6
// speedup vs baseline: 1.8137x; 1.2930x over previous
#include <cuda_runtime.h>
#include <math.h>
#include <stdint.h>

#define BSZ 2048
#define XS  256
#define HS  512
#define RS  64
#define MS  128
#define KS  64
#define HQ  128   // H/4

// ---------------- device scratch ----------------
__device__ float g_xcu[BSZ * 1024];     // [x, c, 0(128), l2n(u_t)]
__device__ float g_base[BSZ * HQ];
__device__ float g_kWk[MS * HQ];
__device__ float g_ri[BSZ * MS];
__device__ float g_r[BSZ * RS];
__device__ float g_Z[BSZ * 1536];
__device__ float g_G[BSZ * HS];
__device__ float g_ab[BSZ * 2];
__device__ float g_nh[BSZ * HS];
__device__ float g_hw[BSZ * RS];
__device__ float g_WT[2048 * 832];      // rows 0..1535 = W_full cols, 1536..2047 = W_full2 cols (tf32-rounded)

__device__ __forceinline__ float sigm(float v) { return 1.0f / (1.0f + expf(-v)); }
__device__ __forceinline__ float gumbelf(float u) {
    return -logf(1e-20f - logf(1e-20f + u));
}
__device__ __forceinline__ float tf32r(float v) {
    uint32_t u;
    asm("cvt.rna.tf32.f32 %0, %1;" : "=r"(u) : "f"(v));
    return __uint_as_float(u);
}
__device__ __forceinline__ uint32_t smem_u32(const void* p) {
    return (uint32_t)__cvta_generic_to_shared(p);
}

// tf32 tensor-core mma (sm_80+ PTX, compiles at compute_100)
__device__ __forceinline__ void mma16n8k8(float c[4], const uint32_t a[4],
                                          uint32_t b0, uint32_t b1) {
    asm volatile(
        "mma.sync.aligned.m16n8k8.row.col.f32.tf32.tf32.f32 "
        "{%0,%1,%2,%3}, {%4,%5,%6,%7}, {%8,%9}, {%0,%1,%2,%3};"
        : "+f"(c[0]), "+f"(c[1]), "+f"(c[2]), "+f"(c[3])
        : "r"(a[0]), "r"(a[1]), "r"(a[2]), "r"(a[3]), "r"(b0), "r"(b1));
}

// ---------------- W transpose (+ tf32 rounding) ----------------
__global__ __launch_bounds__(256) void k_transW(const float* __restrict__ Wf,
                                                const float* __restrict__ Wf2)
{
    __shared__ float tile[32][33];
    const int k0 = blockIdx.x * 32;     // 26
    const int n0 = blockIdx.y * 32;     // 64
    const int tx = threadIdx.x & 31, ty = threadIdx.x >> 5;   // 32 x 8
    const float* W; int ldw, nloc;
    if (n0 < 1536) { W = Wf;  ldw = 1536; nloc = n0; }
    else           { W = Wf2; ldw = 512;  nloc = n0 - 1536; }
#pragma unroll
    for (int i = 0; i < 32; i += 8)
        tile[ty + i][tx] = tf32r(W[(size_t)(k0 + ty + i) * ldw + nloc + tx]);
    __syncthreads();
#pragma unroll
    for (int i = 0; i < 32; i += 8)
        g_WT[(size_t)(n0 + ty + i) * 832 + k0 + tx] = tile[tx][ty + i];
}

// ---------------- mma.sync tf32 GEMM: Z (N=1536) + scaled-G (N=512) ----------------
// grid (16,16): bx = n-tile (0..11 Z, 12..15 G), by = batch tile.
// C[128,128] = A[128,832] @ WT_tile^T; A gathered from x/h/r with alpha/beta
// row scaling for G tiles. 26 double-buffered K=32 stages; B via cp.async.
#define KCH 32
#define APAD 36    // row stride: (4*group + tid) mod 32 unique -> conflict-free frags
__global__ __launch_bounds__(256) void mma_big(
    const float* __restrict__ x, const float* __restrict__ h,
    const float* __restrict__ rbuf, const float* __restrict__ ab,
    const float* __restrict__ bias,
    float* __restrict__ Zout, float* __restrict__ Gout)
{
    extern __shared__ float sm[];           // [2][128][APAD] A + [2][128][APAD] B
    float* Ab[2] = {sm, sm + 128 * APAD};
    float* Bb[2] = {sm + 2 * 128 * APAD, sm + 3 * 128 * APAD};

    const int t = threadIdx.x;
    const int wid = t >> 5, lane = t & 31;
    const int g = lane >> 2, tg = lane & 3;
    const int warp_m = wid & 3, warp_n = wid >> 2;   // 4 x 2 warp grid
    const bool isG = blockIdx.x >= 12;
    const int n0 = blockIdx.x * 128;        // row offset into stacked WT
    const int row0 = blockIdx.y * 128;

    // staging map: row m = t>>1, 16 k-elems at kb
    const int m = t >> 1;
    const int kb = (t & 1) * 16;
    const int bidx = row0 + m;
    float alpha = 1.0f, beta = 1.0f;
    if (isG) { alpha = ab[bidx * 2]; beta = ab[bidx * 2 + 1]; }

    auto loadA16 = [&](int k0c, float4 v[4]) {
        const float* src; float sc;
        if (k0c < 256)      { src = x    + (size_t)bidx * 256 + k0c + kb;         sc = 1.0f;  }
        else if (k0c < 768) { src = h    + (size_t)bidx * 512 + (k0c - 256) + kb; sc = alpha; }
        else                { src = rbuf + (size_t)bidx * 64  + (k0c - 768) + kb; sc = beta;  }
#pragma unroll
        for (int q = 0; q < 4; q++) {
            float4 w = ((const float4*)src)[q];
            v[q] = make_float4(tf32r(w.x * sc), tf32r(w.y * sc),
                               tf32r(w.z * sc), tf32r(w.w * sc));
        }
    };
    auto stsA = [&](int buf, const float4 v[4]) {
        float* dst = Ab[buf] + m * APAD + kb;
#pragma unroll
        for (int q = 0; q < 4; q++) *(float4*)(dst + q * 4) = v[q];
    };
    auto cpB = [&](int buf, int k0c) {
        uint32_t d = smem_u32(Bb[buf] + m * APAD + kb);
        const float* s = g_WT + (size_t)(n0 + m) * 832 + k0c + kb;
#pragma unroll
        for (int q = 0; q < 4; q++)
            asm volatile("cp.async.cg.shared.global [%0], [%1], 16;"
                         :: "r"(d + q * 16), "l"(s + q * 4));
        asm volatile("cp.async.commit_group;");
    };

    float c[2][8][4];
#pragma unroll
    for (int i = 0; i < 2; i++)
#pragma unroll
        for (int j = 0; j < 8; j++)
#pragma unroll
            for (int q = 0; q < 4; q++) c[i][j][q] = 0.0f;

    // prologue: stage chunk 0
    {
        float4 va[4];
        loadA16(0, va);
        stsA(0, va);
        cpB(0, 0);
    }

    const int NT = 832 / KCH;   // 26
    for (int it = 0; it < NT; it++) {
        const int buf = it & 1;
        asm volatile("cp.async.wait_group 0;");
        __syncthreads();

        float4 va[4];
        if (it + 1 < NT) {
            loadA16((it + 1) * KCH, va);     // LDG overlaps compute
            cpB(buf ^ 1, (it + 1) * KCH);    // async overlaps compute
        }

        const float* Ac = Ab[buf];
        const float* Bc = Bb[buf];
#pragma unroll
        for (int kk = 0; kk < 4; kk++) {
            const int kc = kk * 8;
            uint32_t af[2][4];
#pragma unroll
            for (int i = 0; i < 2; i++) {
                const int rb = warp_m * 32 + i * 16;
                af[i][0] = __float_as_uint(Ac[(rb + g) * APAD + kc + tg]);
                af[i][1] = __float_as_uint(Ac[(rb + g + 8) * APAD + kc + tg]);
                af[i][2] = __float_as_uint(Ac[(rb + g) * APAD + kc + tg + 4]);
                af[i][3] = __float_as_uint(Ac[(rb + g + 8) * APAD + kc + tg + 4]);
            }
#pragma unroll
            for (int j = 0; j < 8; j++) {
                const int nb = warp_n * 64 + j * 8 + g;
                uint32_t b0 = __float_as_uint(Bc[nb * APAD + kc + tg]);
                uint32_t b1 = __float_as_uint(Bc[nb * APAD + kc + tg + 4]);
                mma16n8k8(c[0][j], af[0], b0, b1);
                mma16n8k8(c[1][j], af[1], b0, b1);
            }
        }

        if (it + 1 < NT) {
            __syncthreads();        // everyone done reading buf^1 from iter it-1
            stsA(buf ^ 1, va);
        }
    }

    // epilogue: register accumulators -> global (float2 per fragment row)
#pragma unroll
    for (int i = 0; i < 2; i++) {
        const int r0a = row0 + warp_m * 32 + i * 16 + g;
#pragma unroll
        for (int j = 0; j < 8; j++) {
            const int cl = warp_n * 64 + j * 8 + 2 * tg;
            if (!isG) {
                const int gcol = n0 + cl;
                float bz0 = bias[gcol], bz1 = bias[gcol + 1];
                *(float2*)(Zout + (size_t)r0a * 1536 + gcol) =
                    make_float2(c[i][j][0] + bz0, c[i][j][1] + bz1);
                *(float2*)(Zout + (size_t)(r0a + 8) * 1536 + gcol) =
                    make_float2(c[i][j][2] + bz0, c[i][j][3] + bz1);
            } else {
                const int gcol = (n0 - 1536) + cl;
                *(float2*)(Gout + (size_t)r0a * 512 + gcol) =
                    make_float2(c[i][j][0], c[i][j][1]);
                *(float2*)(Gout + (size_t)(r0a + 8) * 512 + gcol) =
                    make_float2(c[i][j][2], c[i][j][3]);
            }
        }
    }
}

// ---------------- SIMT GEMM (base = xcu @ W_fc) ----------------
__device__ __forceinline__ void gemm_inner(const float (*As)[128], const float (*Bs)[128],
                                           float acc[8][8], int tx, int ty)
{
#pragma unroll
    for (int kk = 0; kk < 8; kk++) {
        float4 a0 = *(const float4*)&As[kk][ty * 8];
        float4 a1 = *(const float4*)&As[kk][ty * 8 + 4];
        float4 b0 = *(const float4*)&Bs[kk][tx * 8];
        float4 b1 = *(const float4*)&Bs[kk][tx * 8 + 4];
        float av[8] = {a0.x, a0.y, a0.z, a0.w, a1.x, a1.y, a1.z, a1.w};
        float bv[8] = {b0.x, b0.y, b0.z, b0.w, b1.x, b1.y, b1.z, b1.w};
#pragma unroll
        for (int i = 0; i < 8; i++)
#pragma unroll
            for (int j = 0; j < 8; j++) acc[i][j] += av[i] * bv[j];
    }
}

__global__ __launch_bounds__(256, 2) void gemm_plain(
    const float* __restrict__ A, int lda,
    const float* __restrict__ B, int ldb,
    const float* __restrict__ bias,
    float* __restrict__ C, int ldc, int Kk)
{
    __shared__ float As[2][8][128];
    __shared__ float Bs[2][8][128];
    const int tid = threadIdx.x;
    const int tx = tid & 15, ty = tid >> 4;
    const int row0 = blockIdx.y * 128, col0 = blockIdx.x * 128;
    const int arow = tid >> 1, acol = (tid & 1) * 4;
    const int brow = tid >> 5, bcol = (tid & 31) * 4;

    const float* Aptr = A + (size_t)(row0 + arow) * lda + acol;
    const float* Bptr = B + (size_t)brow * ldb + col0 + bcol;

    float acc[8][8];
#pragma unroll
    for (int i = 0; i < 8; i++)
#pragma unroll
        for (int j = 0; j < 8; j++) acc[i][j] = 0.0f;

    float4 ra = *(const float4*)Aptr;
    float4 rb = *(const float4*)Bptr;
    As[0][acol + 0][arow] = ra.x; As[0][acol + 1][arow] = ra.y;
    As[0][acol + 2][arow] = ra.z; As[0][acol + 3][arow] = ra.w;
    *(float4*)&Bs[0][brow][bcol] = rb;
    __syncthreads();

    const int nt = Kk / 8;
    for (int i = 0; i < nt; i++) {
        int cur = i & 1;
        if (i + 1 < nt) {
            ra = *(const float4*)(Aptr + (i + 1) * 8);
            rb = *(const float4*)(Bptr + (size_t)(i + 1) * 8 * ldb);
        }
        gemm_inner(As[cur], Bs[cur], acc, tx, ty);
        if (i + 1 < nt) {
            int nxt = cur ^ 1;
            As[nxt][acol + 0][arow] = ra.x; As[nxt][acol + 1][arow] = ra.y;
            As[nxt][acol + 2][arow] = ra.z; As[nxt][acol + 3][arow] = ra.w;
            *(float4*)&Bs[nxt][brow][bcol] = rb;
            __syncthreads();
        }
    }

    float bv[8];
#pragma unroll
    for (int j = 0; j < 8; j++) bv[j] = bias ? bias[col0 + tx * 8 + j] : 0.0f;
#pragma unroll
    for (int i = 0; i < 8; i++) {
        float* crow = C + (size_t)(row0 + ty * 8 + i) * ldc + col0 + tx * 8;
        float4 o0 = make_float4(acc[i][0] + bv[0], acc[i][1] + bv[1],
                                acc[i][2] + bv[2], acc[i][3] + bv[3]);
        float4 o1 = make_float4(acc[i][4] + bv[4], acc[i][5] + bv[5],
                                acc[i][6] + bv[6], acc[i][7] + bv[7]);
        *(float4*)crow = o0; *(float4*)(crow + 4) = o1;
    }
}

// ---------------- fused head + selection + alpha/beta ----------------
struct HSmem {
    float hm[128][65];
    float wm[64][128];
    float part[128][17];
    float red[256];
    float ri[128];
    float rs[64];
};

__global__ __launch_bounds__(256, 2) void k_headsel(
    const float* __restrict__ x, const float* __restrict__ h,
    const float* __restrict__ hmem, const float* __restrict__ prev,
    const float* __restrict__ noise_sm, const float* __restrict__ noise_sig,
    const float* __restrict__ W_fc, const float* __restrict__ vec_a,
    const float* __restrict__ W_full1, const float* __restrict__ bias1,
    float* __restrict__ out)
{
    extern __shared__ char smem_raw[];
    HSmem& S = *(HSmem*)smem_raw;
    const int b = blockIdx.x;
    const int t = threadIdx.x;
    const int tx = t & 15, ty = t >> 4;

    {
        const float4* src = (const float4*)(hmem + (size_t)b * (MS * RS));
#pragma unroll
        for (int i = 0; i < 8; i++) {
            int idx = t + i * 256;
            float4 v = src[idx];
            int m = idx >> 4;
            int rr = (idx & 15) * 4;
            S.hm[m][rr] = v.x; S.hm[m][rr + 1] = v.y;
            S.hm[m][rr + 2] = v.z; S.hm[m][rr + 3] = v.w;
        }
    }
    {
        const float4* wsrc = (const float4*)(W_fc + 832 * HQ);
#pragma unroll
        for (int i = 0; i < 8; i++) {
            int idx = t + i * 256;
            float4 v = wsrc[idx];
            int rr = idx >> 5;
            int kk = (idx & 31) * 4;
            *(float4*)&S.wm[rr][kk] = v;
        }
    }
    __syncthreads();

    float acc[8][8];
#pragma unroll
    for (int i = 0; i < 8; i++)
#pragma unroll
        for (int j = 0; j < 8; j++) acc[i][j] = 0.0f;
#pragma unroll 4
    for (int rr = 0; rr < 64; rr++) {
        float av[8];
#pragma unroll
        for (int i = 0; i < 8; i++) av[i] = S.hm[ty * 8 + i][rr];
        float4 b0 = *(const float4*)&S.wm[rr][tx * 8];
        float4 b1 = *(const float4*)&S.wm[rr][tx * 8 + 4];
        float bvv[8] = {b0.x, b0.y, b0.z, b0.w, b1.x, b1.y, b1.z, b1.w};
#pragma unroll
        for (int i = 0; i < 8; i++)
#pragma unroll
            for (int j = 0; j < 8; j++) acc[i][j] += av[i] * bvv[j];
    }

    {
        float4 bs0 = *(const float4*)(g_base + b * HQ + tx * 8);
        float4 bs1 = *(const float4*)(g_base + b * HQ + tx * 8 + 4);
        float4 va0 = *(const float4*)(vec_a + tx * 8);
        float4 va1 = *(const float4*)(vec_a + tx * 8 + 4);
        float bj[8] = {bs0.x, bs0.y, bs0.z, bs0.w, bs1.x, bs1.y, bs1.z, bs1.w};
        float vj[8] = {va0.x, va0.y, va0.z, va0.w, va1.x, va1.y, va1.z, va1.w};
#pragma unroll
        for (int i = 0; i < 8; i++) {
            int m = ty * 8 + i;
            float4 kw0 = *(const float4*)(g_kWk + m * HQ + tx * 8);
            float4 kw1 = *(const float4*)(g_kWk + m * HQ + tx * 8 + 4);
            float kw[8] = {kw0.x, kw0.y, kw0.z, kw0.w, kw1.x, kw1.y, kw1.z, kw1.w};
            float hp = 0.0f;
#pragma unroll
            for (int j = 0; j < 8; j++)
                hp += tanhf(acc[i][j] + bj[j] + kw[j]) * vj[j];
            S.part[m][tx] = hp;
        }
    }
    __syncthreads();

    float hv = 0.0f;
    if (t < MS) {
#pragma unroll
        for (int q = 0; q < 16; q++) hv += S.part[t][q];
        hv -= prev[(size_t)b * MS + t] * 100.0f;
    }
    {
        float v = (t < MS) ? hv * hv : 0.0f;
        S.red[t] = v; __syncthreads();
        for (int s = 128; s > 0; s >>= 1) {
            if (t < s) S.red[t] += S.red[t + s];
            __syncthreads();
        }
        float nrm = fmaxf(sqrtf(S.red[0]), 1e-12f);
        __syncthreads();
        if (t < MS) hv /= nrm;
    }
    float z = (t < MS) ? hv + gumbelf(noise_sm[(size_t)b * MS + t]) : -INFINITY;
    float y = 0.0f;
    {
        S.red[t] = z; __syncthreads();
        for (int s = 128; s > 0; s >>= 1) {
            if (t < s) S.red[t] = fmaxf(S.red[t], S.red[t + s]);
            __syncthreads();
        }
        float zmax = S.red[0]; __syncthreads();
        float e = (t < MS) ? expf(z - zmax) : 0.0f;
        S.red[t] = e; __syncthreads();
        for (int s = 128; s > 0; s >>= 1) {
            if (t < s) S.red[t] += S.red[t + s];
            __syncthreads();
        }
        float es = S.red[0]; __syncthreads();
        y = e / es;
        S.red[t] = (t < MS) ? y : 0.0f; __syncthreads();
        for (int s = 128; s > 0; s >>= 1) {
            if (t < s) S.red[t] = fmaxf(S.red[t], S.red[t + s]);
            __syncthreads();
        }
        float ymax = S.red[0]; __syncthreads();
        if (t < MS) {
            float hard = (y == ymax) ? 1.0f : 0.0f;
            float ri = (hard - y) + y;
            S.ri[t] = ri;
            g_ri[(size_t)b * MS + t] = ri;
        }
    }
    __syncthreads();

    if (t < RS) {
        float a = 0.0f;
#pragma unroll 8
        for (int m = 0; m < MS; m++) a += S.ri[m] * S.hm[m][t];
        S.rs[t] = a;
        g_r[(size_t)b * RS + t] = a;
        out[(size_t)b * 576 + HS + t] = a;
    }
    __syncthreads();

    {
        float s0 = 0.0f, s1 = 0.0f;
        for (int cI = t; cI < 832; cI += 256) {
            float v;
            if (cI < 256)      v = x[(size_t)b * XS + cI];
            else if (cI < 768) v = h[(size_t)b * HS + (cI - 256)];
            else               v = S.rs[cI - 768];
            s0 += v * W_full1[cI * 2 + 0];
            s1 += v * W_full1[cI * 2 + 1];
        }
        S.red[t] = s0; __syncthreads();
        for (int s = 128; s > 0; s >>= 1) {
            if (t < s) S.red[t] += S.red[t + s];
            __syncthreads();
        }
        float S0 = S.red[0]; __syncthreads();
        S.red[t] = s1; __syncthreads();
        for (int s = 128; s > 0; s >>= 1) {
            if (t < s) S.red[t] += S.red[t + s];
            __syncthreads();
        }
        float S1 = S.red[0];
        if (t == 0)
            g_ab[b * 2 + 0] = sigm((S0 + bias1[0] + gumbelf(noise_sig[b * 2 + 0])) * (10.0f / 3.0f));
        if (t == 1)
            g_ab[b * 2 + 1] = sigm((S1 + bias1[1] + gumbelf(noise_sig[b * 2 + 1])) * (10.0f / 3.0f));
    }
}

// ---------------- small kernels ----------------
__global__ void k_prep(const float* __restrict__ x, const float* __restrict__ c,
                       const float* __restrict__ u)
{
    __shared__ float red[128];
    int b = blockIdx.x, t = threadIdx.x;
    float uv = u[b * MS + t];
    red[t] = uv * uv; __syncthreads();
    for (int s = 64; s > 0; s >>= 1) {
        if (t < s) red[t] += red[t + s];
        __syncthreads();
    }
    float denom = fmaxf(sqrtf(red[0]), 1e-12f);
    float* row = g_xcu + (size_t)b * 1024;
    for (int i = t; i < XS; i += 128) row[i] = x[(size_t)b * XS + i];
    for (int i = t; i < HS; i += 128) row[XS + i] = c[(size_t)b * HS + i];
    row[768 + t] = 0.0f;
    row[896 + t] = uv / denom;
}

__global__ void k_kwk(const float* __restrict__ keys, const float* __restrict__ W_fc)
{
    int m = blockIdx.x, t = threadIdx.x;
    float a = 0.0f;
#pragma unroll 8
    for (int r = 0; r < KS; r++)
        a += keys[m * KS + r] * W_fc[(768 + r) * HQ + t];
    g_kWk[m * HQ + t] = a;
}

__global__ void k_epi(const float* __restrict__ c, const float* __restrict__ bias2,
                      float* __restrict__ out)
{
    int b = blockIdx.x, t = threadIdx.x;   // 256 threads
    for (int j = t; j < HS; j += 256) {
        size_t bj = (size_t)b * HS + j;
        float pre = g_G[bj] + bias2[j];
        float nc0 = tanhf(pre);
        float zi = g_Z[(size_t)b * 1536 + j];
        float zf = g_Z[(size_t)b * 1536 + 512 + j];
        float zo = g_Z[(size_t)b * 1536 + 1024 + j];
        float cc = c[bj];
        float ncv = cc * sigm(zf + 1.0f) + sigm(zi) * nc0;
        float nh = tanhf(ncv) * sigm(zo);
        out[(size_t)b * 576 + j] = nh;
        g_nh[bj] = nh;
    }
}

__global__ __launch_bounds__(256) void k_hw(
    const float* __restrict__ x, const float* __restrict__ W_fc1,
    const float* __restrict__ b_fc1)
{
    __shared__ float Ws[64][64];
    __shared__ float Asb[16][68];
    const int b0 = blockIdx.x * 16;
    const int t = threadIdx.x;
    const int n = t & 63, bl = t >> 6;
    float acc[4] = {0.0f, 0.0f, 0.0f, 0.0f};

    for (int k0 = 0; k0 < 768; k0 += 64) {
#pragma unroll
        for (int i = 0; i < 4; i++) {
            int idx = t + i * 256;
            int row = idx >> 4, c4 = (idx & 15) * 4;
            *(float4*)&Ws[row][c4] = *(const float4*)(W_fc1 + (size_t)(k0 + row) * RS + c4);
        }
        {
            int idx = t;
            int row = idx >> 4, c4 = (idx & 15) * 4;
            int gb = b0 + row, gk = k0 + c4;
            float4 v;
            if (gk < 256) v = *(const float4*)(x + (size_t)gb * XS + gk);
            else          v = *(const float4*)(g_nh + (size_t)gb * HS + (gk - 256));
            *(float4*)&Asb[row][c4] = v;
        }
        __syncthreads();
#pragma unroll 16
        for (int kk = 0; kk < 64; kk++) {
            float w = Ws[kk][n];
#pragma unroll
            for (int i = 0; i < 4; i++) acc[i] += Asb[bl * 4 + i][kk] * w;
        }
        __syncthreads();
    }
    float bb = b_fc1[n];
#pragma unroll
    for (int i = 0; i < 4; i++)
        g_hw[(size_t)(b0 + bl * 4 + i) * RS + n] = acc[i] + bb;
}

__global__ void k_hmem(const float* __restrict__ hmem, float* __restrict__ out)
{
    int idx = blockIdx.x * blockDim.x + threadIdx.x;
    int q = idx & 15;
    int m = (idx >> 4) & 127;
    int b = idx >> 11;
    float w = g_ri[b * MS + m];
    float4 hv = ((const float4*)hmem)[(size_t)idx];
    float4 o = hv;
    if (w != 0.0f) {
        float om = 1.0f - w;
        float4 hw = ((const float4*)g_hw)[b * 16 + q];
        o.x = hw.x * w + hv.x * om;
        o.y = hw.y * w + hv.y * om;
        o.z = hw.z * w + hv.z * om;
        o.w = hw.w * w + hv.w * om;
    }
    ((float4*)out)[(size_t)(BSZ * 576 / 4) + idx] = o;
}

// ---------------- launch ----------------
extern "C" void kernel_launch(void* const* d_in, const int* in_sizes, int n_in,
                              void* d_out, int out_size)
{
    const float* x        = (const float*)d_in[0];
    const float* h        = (const float*)d_in[1];
    const float* c        = (const float*)d_in[2];
    const float* hmem     = (const float*)d_in[3];
    const float* u_t      = (const float*)d_in[4];
    const float* prev     = (const float*)d_in[5];
    const float* W_full   = (const float*)d_in[6];
    const float* bias     = (const float*)d_in[7];
    const float* W_full1  = (const float*)d_in[8];
    const float* bias1    = (const float*)d_in[9];
    const float* W_full2  = (const float*)d_in[10];
    const float* bias2    = (const float*)d_in[11];
    const float* keys     = (const float*)d_in[12];
    const float* vec_a    = (const float*)d_in[13];
    const float* W_fc     = (const float*)d_in[14];
    const float* b_fc     = (const float*)d_in[15];
    const float* W_fc1    = (const float*)d_in[16];
    const float* b_fc1    = (const float*)d_in[17];
    const float* noise_sm = (const float*)d_in[18];
    const float* noise_sig= (const float*)d_in[19];
    float* out = (float*)d_out;

    float *p_xcu, *p_base, *p_r, *p_ab, *p_Z, *p_G;
    cudaGetSymbolAddress((void**)&p_xcu,  g_xcu);
    cudaGetSymbolAddress((void**)&p_base, g_base);
    cudaGetSymbolAddress((void**)&p_r,    g_r);
    cudaGetSymbolAddress((void**)&p_ab,   g_ab);
    cudaGetSymbolAddress((void**)&p_Z,    g_Z);
    cudaGetSymbolAddress((void**)&p_G,    g_G);

    const int MMASMEM = 4 * 128 * APAD * 4;   // 73728 B

    static bool attr_set = false;
    if (!attr_set) {
        cudaFuncSetAttribute(k_headsel, cudaFuncAttributeMaxDynamicSharedMemorySize,
                             (int)sizeof(HSmem));
        cudaFuncSetAttribute(mma_big, cudaFuncAttributeMaxDynamicSharedMemorySize, MMASMEM);
        attr_set = true;
    }

    // 0) weight transpose (+tf32 rounding)
    k_transW<<<dim3(26, 64), 256>>>(W_full, W_full2);

    // 1) xcu + keys@W_k
    k_prep<<<BSZ, 128>>>(x, c, u_t);
    k_kwk<<<MS, HQ>>>(keys, W_fc);

    // 2) base = xcu @ W_fc + b_fc
    gemm_plain<<<dim3(1, BSZ / 128), 256>>>(p_xcu, 1024, W_fc, HQ, b_fc, p_base, HQ, 1024);

    // 3) fused head + selection + alpha/beta (fp32 — argmax path stays exact)
    k_headsel<<<BSZ, 256, sizeof(HSmem)>>>(x, h, hmem, prev, noise_sm, noise_sig,
                                           W_fc, vec_a, W_full1, bias1, out);

    // 4) tensor-core tf32 Z + scaled-G GEMM
    mma_big<<<dim3(16, 16), 256, MMASMEM>>>(x, h, p_r, p_ab, bias, p_Z, p_G);

    // 5) cell epilogue -> new_h
    k_epi<<<BSZ, 256>>>(c, bias2, out);

    // 6) h_w ; 7) hmem blend-copy
    k_hw<<<BSZ / 16, 256>>>(x, W_fc1, b_fc1);
    k_hmem<<<(BSZ * MS * 16) / 256, 256>>>(hmem, out);
}

// round 7
// speedup vs baseline: 2.2473x; 1.2391x over previous
#include <cuda_runtime.h>
#include <math.h>
#include <stdint.h>

#define BSZ 2048
#define XS  256
#define HS  512
#define RS  64
#define MS  128
#define KS  64
#define HQ  128   // H/4

// ---------------- device scratch ----------------
__device__ float g_xcu[BSZ * 1024];     // [x, c, (junk 128), l2n(u_t)]
__device__ float g_bp[7 * BSZ * HQ];    // split-K partials for base
__device__ float g_base[BSZ * HQ];
__device__ float g_kWk[MS * HQ];
__device__ float g_ri[BSZ * MS];
__device__ float g_r[BSZ * RS];
__device__ float g_Z[BSZ * 1536];
__device__ float g_G[BSZ * HS];
__device__ float g_ab[BSZ * 2];
__device__ float g_nh[BSZ * HS];
__device__ float g_hw[BSZ * RS];
__device__ float g_WT[2048 * 832];      // rows 0..1535 = W_full cols, 1536..2047 = W_full2 cols (tf32-rounded)

__device__ __forceinline__ float sigm(float v) { return 1.0f / (1.0f + expf(-v)); }
__device__ __forceinline__ float gumbelf(float u) {
    return -logf(1e-20f - logf(1e-20f + u));
}
__device__ __forceinline__ float tf32r(float v) {
    uint32_t u;
    asm("cvt.rna.tf32.f32 %0, %1;" : "=r"(u) : "f"(v));
    return __uint_as_float(u);
}
__device__ __forceinline__ uint32_t smem_u32(const void* p) {
    return (uint32_t)__cvta_generic_to_shared(p);
}

// tf32 tensor-core mma (sm_80+ PTX, compiles at compute_100)
__device__ __forceinline__ void mma16n8k8(float c[4], const uint32_t a[4],
                                          uint32_t b0, uint32_t b1) {
    asm volatile(
        "mma.sync.aligned.m16n8k8.row.col.f32.tf32.tf32.f32 "
        "{%0,%1,%2,%3}, {%4,%5,%6,%7}, {%8,%9}, {%0,%1,%2,%3};"
        : "+f"(c[0]), "+f"(c[1]), "+f"(c[2]), "+f"(c[3])
        : "r"(a[0]), "r"(a[1]), "r"(a[2]), "r"(a[3]), "r"(b0), "r"(b1));
}

// ---------------- W transpose (+ tf32 rounding) ----------------
__global__ __launch_bounds__(256) void k_transW(const float* __restrict__ Wf,
                                                const float* __restrict__ Wf2)
{
    __shared__ float tile[32][33];
    const int k0 = blockIdx.x * 32;     // 26
    const int n0 = blockIdx.y * 32;     // 64
    const int tx = threadIdx.x & 31, ty = threadIdx.x >> 5;   // 32 x 8
    const float* W; int ldw, nloc;
    if (n0 < 1536) { W = Wf;  ldw = 1536; nloc = n0; }
    else           { W = Wf2; ldw = 512;  nloc = n0 - 1536; }
#pragma unroll
    for (int i = 0; i < 32; i += 8)
        tile[ty + i][tx] = tf32r(W[(size_t)(k0 + ty + i) * ldw + nloc + tx]);
    __syncthreads();
#pragma unroll
    for (int i = 0; i < 32; i += 8)
        g_WT[(size_t)(n0 + ty + i) * 832 + k0 + tx] = tile[tx][ty + i];
}

// ---------------- mma.sync tf32 GEMM: Z (N=1536) + scaled-G (N=512) ----------------
#define KCH 32
#define APAD 36
__global__ __launch_bounds__(256) void mma_big(
    const float* __restrict__ x, const float* __restrict__ h,
    const float* __restrict__ rbuf, const float* __restrict__ ab,
    const float* __restrict__ bias,
    float* __restrict__ Zout, float* __restrict__ Gout)
{
    extern __shared__ float sm[];           // [2][128][APAD] A + [2][128][APAD] B
    float* Ab[2] = {sm, sm + 128 * APAD};
    float* Bb[2] = {sm + 2 * 128 * APAD, sm + 3 * 128 * APAD};

    const int t = threadIdx.x;
    const int wid = t >> 5, lane = t & 31;
    const int g = lane >> 2, tg = lane & 3;
    const int warp_m = wid & 3, warp_n = wid >> 2;   // 4 x 2 warp grid
    const bool isG = blockIdx.x >= 12;
    const int n0 = blockIdx.x * 128;        // row offset into stacked WT
    const int row0 = blockIdx.y * 128;

    const int m = t >> 1;
    const int kb = (t & 1) * 16;
    const int bidx = row0 + m;
    float alpha = 1.0f, beta = 1.0f;
    if (isG) { alpha = ab[bidx * 2]; beta = ab[bidx * 2 + 1]; }

    auto loadA16 = [&](int k0c, float4 v[4]) {
        const float* src; float sc;
        if (k0c < 256)      { src = x    + (size_t)bidx * 256 + k0c + kb;         sc = 1.0f;  }
        else if (k0c < 768) { src = h    + (size_t)bidx * 512 + (k0c - 256) + kb; sc = alpha; }
        else                { src = rbuf + (size_t)bidx * 64  + (k0c - 768) + kb; sc = beta;  }
#pragma unroll
        for (int q = 0; q < 4; q++) {
            float4 w = ((const float4*)src)[q];
            v[q] = make_float4(tf32r(w.x * sc), tf32r(w.y * sc),
                               tf32r(w.z * sc), tf32r(w.w * sc));
        }
    };
    auto stsA = [&](int buf, const float4 v[4]) {
        float* dst = Ab[buf] + m * APAD + kb;
#pragma unroll
        for (int q = 0; q < 4; q++) *(float4*)(dst + q * 4) = v[q];
    };
    auto cpB = [&](int buf, int k0c) {
        uint32_t d = smem_u32(Bb[buf] + m * APAD + kb);
        const float* s = g_WT + (size_t)(n0 + m) * 832 + k0c + kb;
#pragma unroll
        for (int q = 0; q < 4; q++)
            asm volatile("cp.async.cg.shared.global [%0], [%1], 16;"
                         :: "r"(d + q * 16), "l"(s + q * 4));
        asm volatile("cp.async.commit_group;");
    };

    float c[2][8][4];
#pragma unroll
    for (int i = 0; i < 2; i++)
#pragma unroll
        for (int j = 0; j < 8; j++)
#pragma unroll
            for (int q = 0; q < 4; q++) c[i][j][q] = 0.0f;

    {
        float4 va[4];
        loadA16(0, va);
        stsA(0, va);
        cpB(0, 0);
    }

    const int NT = 832 / KCH;   // 26
    for (int it = 0; it < NT; it++) {
        const int buf = it & 1;
        asm volatile("cp.async.wait_group 0;");
        __syncthreads();

        float4 va[4];
        if (it + 1 < NT) {
            loadA16((it + 1) * KCH, va);
            cpB(buf ^ 1, (it + 1) * KCH);
        }

        const float* Ac = Ab[buf];
        const float* Bc = Bb[buf];
#pragma unroll
        for (int kk = 0; kk < 4; kk++) {
            const int kc = kk * 8;
            uint32_t af[2][4];
#pragma unroll
            for (int i = 0; i < 2; i++) {
                const int rb = warp_m * 32 + i * 16;
                af[i][0] = __float_as_uint(Ac[(rb + g) * APAD + kc + tg]);
                af[i][1] = __float_as_uint(Ac[(rb + g + 8) * APAD + kc + tg]);
                af[i][2] = __float_as_uint(Ac[(rb + g) * APAD + kc + tg + 4]);
                af[i][3] = __float_as_uint(Ac[(rb + g + 8) * APAD + kc + tg + 4]);
            }
#pragma unroll
            for (int j = 0; j < 8; j++) {
                const int nb = warp_n * 64 + j * 8 + g;
                uint32_t b0 = __float_as_uint(Bc[nb * APAD + kc + tg]);
                uint32_t b1 = __float_as_uint(Bc[nb * APAD + kc + tg + 4]);
                mma16n8k8(c[0][j], af[0], b0, b1);
                mma16n8k8(c[1][j], af[1], b0, b1);
            }
        }

        if (it + 1 < NT) {
            __syncthreads();
            stsA(buf ^ 1, va);
        }
    }

#pragma unroll
    for (int i = 0; i < 2; i++) {
        const int r0a = row0 + warp_m * 32 + i * 16 + g;
#pragma unroll
        for (int j = 0; j < 8; j++) {
            const int cl = warp_n * 64 + j * 8 + 2 * tg;
            if (!isG) {
                const int gcol = n0 + cl;
                float bz0 = bias[gcol], bz1 = bias[gcol + 1];
                *(float2*)(Zout + (size_t)r0a * 1536 + gcol) =
                    make_float2(c[i][j][0] + bz0, c[i][j][1] + bz1);
                *(float2*)(Zout + (size_t)(r0a + 8) * 1536 + gcol) =
                    make_float2(c[i][j][2] + bz0, c[i][j][3] + bz1);
            } else {
                const int gcol = (n0 - 1536) + cl;
                *(float2*)(Gout + (size_t)r0a * 512 + gcol) =
                    make_float2(c[i][j][0], c[i][j][1]);
                *(float2*)(Gout + (size_t)(r0a + 8) * 512 + gcol) =
                    make_float2(c[i][j][2], c[i][j][3]);
            }
        }
    }
}

// ---------------- split-K base GEMM: g_bp[s] = xcu[:, slice s] @ W_fc[slice s] ----
// Effective K = 896 (skip zero-pad cols 768..895). 7 slices x 16 row tiles = 112 blocks.
__global__ __launch_bounds__(256, 2) void gemm_base(const float* __restrict__ W_fc)
{
    __shared__ float As[2][8][128];
    __shared__ float Bs[2][8][128];
    const int tid = threadIdx.x;
    const int tx = tid & 15, ty = tid >> 4;
    const int s = blockIdx.x;                 // 0..6
    const int row0 = blockIdx.y * 128;
    const int cs = (s < 6) ? s * 128 : 896;   // source column offset in xcu / row offset in W_fc
    const int arow = tid >> 1, acol = (tid & 1) * 4;
    const int brow = tid >> 5, bcol = (tid & 31) * 4;

    const float* Aptr = g_xcu + (size_t)(row0 + arow) * 1024 + cs + acol;
    const float* Bptr = W_fc + (size_t)(cs + brow) * HQ + bcol;
    float* C = g_bp + (size_t)s * (BSZ * HQ);

    float acc[8][8];
#pragma unroll
    for (int i = 0; i < 8; i++)
#pragma unroll
        for (int j = 0; j < 8; j++) acc[i][j] = 0.0f;

    float4 ra = *(const float4*)Aptr;
    float4 rb = *(const float4*)Bptr;
    As[0][acol + 0][arow] = ra.x; As[0][acol + 1][arow] = ra.y;
    As[0][acol + 2][arow] = ra.z; As[0][acol + 3][arow] = ra.w;
    *(float4*)&Bs[0][brow][bcol] = rb;
    __syncthreads();

    const int nt = 128 / 8;   // 16
    for (int i = 0; i < nt; i++) {
        int cur = i & 1;
        if (i + 1 < nt) {
            ra = *(const float4*)(Aptr + (i + 1) * 8);
            rb = *(const float4*)(Bptr + (size_t)(i + 1) * 8 * HQ);
        }
#pragma unroll
        for (int kk = 0; kk < 8; kk++) {
            float4 a0 = *(const float4*)&As[cur][kk][ty * 8];
            float4 a1 = *(const float4*)&As[cur][kk][ty * 8 + 4];
            float4 b0 = *(const float4*)&Bs[cur][kk][tx * 8];
            float4 b1 = *(const float4*)&Bs[cur][kk][tx * 8 + 4];
            float av[8] = {a0.x, a0.y, a0.z, a0.w, a1.x, a1.y, a1.z, a1.w};
            float bv[8] = {b0.x, b0.y, b0.z, b0.w, b1.x, b1.y, b1.z, b1.w};
#pragma unroll
            for (int ii = 0; ii < 8; ii++)
#pragma unroll
                for (int jj = 0; jj < 8; jj++) acc[ii][jj] += av[ii] * bv[jj];
        }
        if (i + 1 < nt) {
            int nxt = cur ^ 1;
            As[nxt][acol + 0][arow] = ra.x; As[nxt][acol + 1][arow] = ra.y;
            As[nxt][acol + 2][arow] = ra.z; As[nxt][acol + 3][arow] = ra.w;
            *(float4*)&Bs[nxt][brow][bcol] = rb;
            __syncthreads();
        }
    }

#pragma unroll
    for (int i = 0; i < 8; i++) {
        float* crow = C + (size_t)(row0 + ty * 8 + i) * HQ + tx * 8;
        *(float4*)crow = make_float4(acc[i][0], acc[i][1], acc[i][2], acc[i][3]);
        *(float4*)(crow + 4) = make_float4(acc[i][4], acc[i][5], acc[i][6], acc[i][7]);
    }
}

__global__ void k_base_reduce(const float* __restrict__ b_fc)
{
    int i = blockIdx.x * 256 + threadIdx.x;   // 0..262143
    float a = b_fc[i & 127];
#pragma unroll
    for (int s = 0; s < 7; s++) a += g_bp[(size_t)s * (BSZ * HQ) + i];
    g_base[i] = a;
}

// ---------------- fused head + selection + alpha/beta ----------------
struct HSmem {
    float hm[128][65];
    float wm[64][128];
    float part[128][17];
    float red[256];
    float ri[128];
    float rs[64];
};

__global__ __launch_bounds__(256, 2) void k_headsel(
    const float* __restrict__ x, const float* __restrict__ h,
    const float* __restrict__ hmem, const float* __restrict__ prev,
    const float* __restrict__ noise_sm, const float* __restrict__ noise_sig,
    const float* __restrict__ W_fc, const float* __restrict__ vec_a,
    const float* __restrict__ W_full1, const float* __restrict__ bias1,
    float* __restrict__ out)
{
    extern __shared__ char smem_raw[];
    HSmem& S = *(HSmem*)smem_raw;
    const int b = blockIdx.x;
    const int t = threadIdx.x;
    const int tx = t & 15, ty = t >> 4;

    {
        const float4* src = (const float4*)(hmem + (size_t)b * (MS * RS));
#pragma unroll
        for (int i = 0; i < 8; i++) {
            int idx = t + i * 256;
            float4 v = src[idx];
            int m = idx >> 4;
            int rr = (idx & 15) * 4;
            S.hm[m][rr] = v.x; S.hm[m][rr + 1] = v.y;
            S.hm[m][rr + 2] = v.z; S.hm[m][rr + 3] = v.w;
        }
    }
    {
        const float4* wsrc = (const float4*)(W_fc + 832 * HQ);
#pragma unroll
        for (int i = 0; i < 8; i++) {
            int idx = t + i * 256;
            float4 v = wsrc[idx];
            int rr = idx >> 5;
            int kk = (idx & 31) * 4;
            *(float4*)&S.wm[rr][kk] = v;
        }
    }
    __syncthreads();

    float acc[8][8];
#pragma unroll
    for (int i = 0; i < 8; i++)
#pragma unroll
        for (int j = 0; j < 8; j++) acc[i][j] = 0.0f;
#pragma unroll 4
    for (int rr = 0; rr < 64; rr++) {
        float av[8];
#pragma unroll
        for (int i = 0; i < 8; i++) av[i] = S.hm[ty * 8 + i][rr];
        float4 b0 = *(const float4*)&S.wm[rr][tx * 8];
        float4 b1 = *(const float4*)&S.wm[rr][tx * 8 + 4];
        float bvv[8] = {b0.x, b0.y, b0.z, b0.w, b1.x, b1.y, b1.z, b1.w};
#pragma unroll
        for (int i = 0; i < 8; i++)
#pragma unroll
            for (int j = 0; j < 8; j++) acc[i][j] += av[i] * bvv[j];
    }

    {
        float4 bs0 = *(const float4*)(g_base + b * HQ + tx * 8);
        float4 bs1 = *(const float4*)(g_base + b * HQ + tx * 8 + 4);
        float4 va0 = *(const float4*)(vec_a + tx * 8);
        float4 va1 = *(const float4*)(vec_a + tx * 8 + 4);
        float bj[8] = {bs0.x, bs0.y, bs0.z, bs0.w, bs1.x, bs1.y, bs1.z, bs1.w};
        float vj[8] = {va0.x, va0.y, va0.z, va0.w, va1.x, va1.y, va1.z, va1.w};
#pragma unroll
        for (int i = 0; i < 8; i++) {
            int m = ty * 8 + i;
            float4 kw0 = *(const float4*)(g_kWk + m * HQ + tx * 8);
            float4 kw1 = *(const float4*)(g_kWk + m * HQ + tx * 8 + 4);
            float kw[8] = {kw0.x, kw0.y, kw0.z, kw0.w, kw1.x, kw1.y, kw1.z, kw1.w};
            float hp = 0.0f;
#pragma unroll
            for (int j = 0; j < 8; j++)
                hp += tanhf(acc[i][j] + bj[j] + kw[j]) * vj[j];
            S.part[m][tx] = hp;
        }
    }
    __syncthreads();

    float hv = 0.0f;
    if (t < MS) {
#pragma unroll
        for (int q = 0; q < 16; q++) hv += S.part[t][q];
        hv -= prev[(size_t)b * MS + t] * 100.0f;
    }
    {
        float v = (t < MS) ? hv * hv : 0.0f;
        S.red[t] = v; __syncthreads();
        for (int s = 128; s > 0; s >>= 1) {
            if (t < s) S.red[t] += S.red[t + s];
            __syncthreads();
        }
        float nrm = fmaxf(sqrtf(S.red[0]), 1e-12f);
        __syncthreads();
        if (t < MS) hv /= nrm;
    }
    float z = (t < MS) ? hv + gumbelf(noise_sm[(size_t)b * MS + t]) : -INFINITY;
    float y = 0.0f;
    {
        S.red[t] = z; __syncthreads();
        for (int s = 128; s > 0; s >>= 1) {
            if (t < s) S.red[t] = fmaxf(S.red[t], S.red[t + s]);
            __syncthreads();
        }
        float zmax = S.red[0]; __syncthreads();
        float e = (t < MS) ? expf(z - zmax) : 0.0f;
        S.red[t] = e; __syncthreads();
        for (int s = 128; s > 0; s >>= 1) {
            if (t < s) S.red[t] += S.red[t + s];
            __syncthreads();
        }
        float es = S.red[0]; __syncthreads();
        y = e / es;
        S.red[t] = (t < MS) ? y : 0.0f; __syncthreads();
        for (int s = 128; s > 0; s >>= 1) {
            if (t < s) S.red[t] = fmaxf(S.red[t], S.red[t + s]);
            __syncthreads();
        }
        float ymax = S.red[0]; __syncthreads();
        if (t < MS) {
            float hard = (y == ymax) ? 1.0f : 0.0f;
            float ri = (hard - y) + y;
            S.ri[t] = ri;
            g_ri[(size_t)b * MS + t] = ri;
        }
    }
    __syncthreads();

    if (t < RS) {
        float a = 0.0f;
#pragma unroll 8
        for (int m = 0; m < MS; m++) a += S.ri[m] * S.hm[m][t];
        S.rs[t] = a;
        g_r[(size_t)b * RS + t] = a;
        out[(size_t)b * 576 + HS + t] = a;
    }
    __syncthreads();

    {
        float s0 = 0.0f, s1 = 0.0f;
        for (int cI = t; cI < 832; cI += 256) {
            float v;
            if (cI < 256)      v = x[(size_t)b * XS + cI];
            else if (cI < 768) v = h[(size_t)b * HS + (cI - 256)];
            else               v = S.rs[cI - 768];
            s0 += v * W_full1[cI * 2 + 0];
            s1 += v * W_full1[cI * 2 + 1];
        }
        S.red[t] = s0; __syncthreads();
        for (int s = 128; s > 0; s >>= 1) {
            if (t < s) S.red[t] += S.red[t + s];
            __syncthreads();
        }
        float S0 = S.red[0]; __syncthreads();
        S.red[t] = s1; __syncthreads();
        for (int s = 128; s > 0; s >>= 1) {
            if (t < s) S.red[t] += S.red[t + s];
            __syncthreads();
        }
        float S1 = S.red[0];
        if (t == 0)
            g_ab[b * 2 + 0] = sigm((S0 + bias1[0] + gumbelf(noise_sig[b * 2 + 0])) * (10.0f / 3.0f));
        if (t == 1)
            g_ab[b * 2 + 1] = sigm((S1 + bias1[1] + gumbelf(noise_sig[b * 2 + 1])) * (10.0f / 3.0f));
    }
}

// ---------------- small kernels ----------------
__global__ void k_prep(const float* __restrict__ x, const float* __restrict__ c,
                       const float* __restrict__ u)
{
    __shared__ float red[128];
    int b = blockIdx.x, t = threadIdx.x;
    float uv = u[b * MS + t];
    red[t] = uv * uv; __syncthreads();
    for (int s = 64; s > 0; s >>= 1) {
        if (t < s) red[t] += red[t + s];
        __syncthreads();
    }
    float denom = fmaxf(sqrtf(red[0]), 1e-12f);
    float* row = g_xcu + (size_t)b * 1024;
    for (int i = t; i < XS; i += 128) row[i] = x[(size_t)b * XS + i];
    for (int i = t; i < HS; i += 128) row[XS + i] = c[(size_t)b * HS + i];
    row[896 + t] = uv / denom;
}

__global__ void k_kwk(const float* __restrict__ keys, const float* __restrict__ W_fc)
{
    int m = blockIdx.x, t = threadIdx.x;
    float a = 0.0f;
#pragma unroll 8
    for (int r = 0; r < KS; r++)
        a += keys[m * KS + r] * W_fc[(768 + r) * HQ + t];
    g_kWk[m * HQ + t] = a;
}

__global__ void k_epi(const float* __restrict__ c, const float* __restrict__ bias2,
                      float* __restrict__ out)
{
    int b = blockIdx.x, t = threadIdx.x;   // 256 threads
    for (int j = t; j < HS; j += 256) {
        size_t bj = (size_t)b * HS + j;
        float pre = g_G[bj] + bias2[j];
        float nc0 = tanhf(pre);
        float zi = g_Z[(size_t)b * 1536 + j];
        float zf = g_Z[(size_t)b * 1536 + 512 + j];
        float zo = g_Z[(size_t)b * 1536 + 1024 + j];
        float cc = c[bj];
        float ncv = cc * sigm(zf + 1.0f) + sigm(zi) * nc0;
        float nh = tanhf(ncv) * sigm(zo);
        out[(size_t)b * 576 + j] = nh;
        g_nh[bj] = nh;
    }
}

__global__ __launch_bounds__(256) void k_hw(
    const float* __restrict__ x, const float* __restrict__ W_fc1,
    const float* __restrict__ b_fc1)
{
    __shared__ float Ws[64][64];
    __shared__ float Asb[16][68];
    const int b0 = blockIdx.x * 16;
    const int t = threadIdx.x;
    const int n = t & 63, bl = t >> 6;
    float acc[4] = {0.0f, 0.0f, 0.0f, 0.0f};

    for (int k0 = 0; k0 < 768; k0 += 64) {
#pragma unroll
        for (int i = 0; i < 4; i++) {
            int idx = t + i * 256;
            int row = idx >> 4, c4 = (idx & 15) * 4;
            *(float4*)&Ws[row][c4] = *(const float4*)(W_fc1 + (size_t)(k0 + row) * RS + c4);
        }
        {
            int idx = t;
            int row = idx >> 4, c4 = (idx & 15) * 4;
            int gb = b0 + row, gk = k0 + c4;
            float4 v;
            if (gk < 256) v = *(const float4*)(x + (size_t)gb * XS + gk);
            else          v = *(const float4*)(g_nh + (size_t)gb * HS + (gk - 256));
            *(float4*)&Asb[row][c4] = v;
        }
        __syncthreads();
#pragma unroll 16
        for (int kk = 0; kk < 64; kk++) {
            float w = Ws[kk][n];
#pragma unroll
            for (int i = 0; i < 4; i++) acc[i] += Asb[bl * 4 + i][kk] * w;
        }
        __syncthreads();
    }
    float bb = b_fc1[n];
#pragma unroll
    for (int i = 0; i < 4; i++)
        g_hw[(size_t)(b0 + bl * 4 + i) * RS + n] = acc[i] + bb;
}

// bulk copy hmem -> out (overlapped on side stream; selected rows fixed later)
__global__ void k_hmem_copy(const float* __restrict__ hmem, float* __restrict__ out)
{
    size_t idx = (size_t)blockIdx.x * 256 + threadIdx.x;   // float4 idx over B*M*16
    ((float4*)out)[(size_t)(BSZ * 576 / 4) + idx] = ((const float4*)hmem)[idx];
}

// patch selected rows: new_hmem[b][m] = hw[b]*w + hmem[b][m]*(1-w) where ri != 0
__global__ void k_hmem_fix(const float* __restrict__ hmem, float* __restrict__ out)
{
    __shared__ float w[128];
    const int b = blockIdx.x, t = threadIdx.x;
    w[t] = g_ri[(size_t)b * MS + t];
    __syncthreads();
    for (int m = 0; m < MS; m++) {
        float wm = w[m];
        if (wm != 0.0f && t < RS) {
            float hv = hmem[((size_t)b * MS + m) * RS + t];
            float hwv = g_hw[(size_t)b * RS + t];
            out[(size_t)BSZ * 576 + ((size_t)b * MS + m) * RS + t] =
                hwv * wm + hv * (1.0f - wm);
        }
    }
}

// ---------------- launch ----------------
extern "C" void kernel_launch(void* const* d_in, const int* in_sizes, int n_in,
                              void* d_out, int out_size)
{
    const float* x        = (const float*)d_in[0];
    const float* h        = (const float*)d_in[1];
    const float* c        = (const float*)d_in[2];
    const float* hmem     = (const float*)d_in[3];
    const float* u_t      = (const float*)d_in[4];
    const float* prev     = (const float*)d_in[5];
    const float* W_full   = (const float*)d_in[6];
    const float* bias     = (const float*)d_in[7];
    const float* W_full1  = (const float*)d_in[8];
    const float* bias1    = (const float*)d_in[9];
    const float* W_full2  = (const float*)d_in[10];
    const float* bias2    = (const float*)d_in[11];
    const float* keys     = (const float*)d_in[12];
    const float* vec_a    = (const float*)d_in[13];
    const float* W_fc     = (const float*)d_in[14];
    const float* b_fc     = (const float*)d_in[15];
    const float* W_fc1    = (const float*)d_in[16];
    const float* b_fc1    = (const float*)d_in[17];
    const float* noise_sm = (const float*)d_in[18];
    const float* noise_sig= (const float*)d_in[19];
    float* out = (float*)d_out;

    float *p_r, *p_ab, *p_Z, *p_G;
    cudaGetSymbolAddress((void**)&p_r,  g_r);
    cudaGetSymbolAddress((void**)&p_ab, g_ab);
    cudaGetSymbolAddress((void**)&p_Z,  g_Z);
    cudaGetSymbolAddress((void**)&p_G,  g_G);

    const int MMASMEM = 4 * 128 * APAD * 4;   // 73728 B

    static cudaStream_t s2 = nullptr;
    static cudaEvent_t e1 = nullptr, e2 = nullptr;
    static bool init_done = false;
    if (!init_done) {
        cudaFuncSetAttribute(k_headsel, cudaFuncAttributeMaxDynamicSharedMemorySize,
                             (int)sizeof(HSmem));
        cudaFuncSetAttribute(mma_big, cudaFuncAttributeMaxDynamicSharedMemorySize, MMASMEM);
        cudaStreamCreateWithFlags(&s2, cudaStreamNonBlocking);
        cudaEventCreateWithFlags(&e1, cudaEventDisableTiming);
        cudaEventCreateWithFlags(&e2, cudaEventDisableTiming);
        init_done = true;
    }

    // fork: bulk hmem copy on side stream (no dependencies)
    cudaEventRecord(e1, 0);
    cudaStreamWaitEvent(s2, e1, 0);
    k_hmem_copy<<<(BSZ * MS * 16) / 256, 256, 0, s2>>>(hmem, out);
    cudaEventRecord(e2, s2);

    // main chain
    k_transW<<<dim3(26, 64), 256>>>(W_full, W_full2);
    k_prep<<<BSZ, 128>>>(x, c, u_t);
    k_kwk<<<MS, HQ>>>(keys, W_fc);

    gemm_base<<<dim3(7, 16), 256>>>(W_fc);
    k_base_reduce<<<BSZ * HQ / 256, 256>>>(b_fc);

    k_headsel<<<BSZ, 256, sizeof(HSmem)>>>(x, h, hmem, prev, noise_sm, noise_sig,
                                           W_fc, vec_a, W_full1, bias1, out);

    mma_big<<<dim3(16, 16), 256, MMASMEM>>>(x, h, p_r, p_ab, bias, p_Z, p_G);

    k_epi<<<BSZ, 256>>>(c, bias2, out);
    k_hw<<<BSZ / 16, 256>>>(x, W_fc1, b_fc1);

    // join: patch selected hmem rows after bulk copy completed
    cudaStreamWaitEvent(0, e2, 0);
    k_hmem_fix<<<BSZ, 128>>>(hmem, out);
}

// round 9
// speedup vs baseline: 2.7445x; 1.2212x over previous
#include <cuda_runtime.h>
#include <math.h>
#include <stdint.h>

#define BSZ 2048
#define XS  256
#define HS  512
#define RS  64
#define MS  128
#define KS  64
#define HQ  128   // H/4

// ---------------- device scratch ----------------
__device__ float g_xcu[BSZ * 1024];     // [x, c, (junk 128), l2n(u_t)]
__device__ float g_bp[7 * BSZ * HQ];    // split-K partials for base
__device__ float g_base[BSZ * HQ];
__device__ float g_kWk[MS * HQ];
__device__ float g_WmT[MS * KS];        // W_m^T (128 n x 64 k), tf32-rounded
__device__ float g_ri[BSZ * MS];
__device__ float g_r[BSZ * RS];
__device__ float g_Z[BSZ * 1536];
__device__ float g_G[BSZ * HS];
__device__ float g_ab[BSZ * 2];
__device__ float g_nh[BSZ * HS];
__device__ float g_hw[BSZ * RS];
__device__ float g_WT[2048 * 832];      // rows 0..1535 = W_full cols, 1536..2047 = W_full2 cols (tf32)

__device__ __forceinline__ float sigm(float v) { return 1.0f / (1.0f + expf(-v)); }
__device__ __forceinline__ float gumbelf(float u) {
    return -logf(1e-20f - logf(1e-20f + u));
}
__device__ __forceinline__ float tf32r(float v) {
    uint32_t u;
    asm("cvt.rna.tf32.f32 %0, %1;" : "=r"(u) : "f"(v));
    return __uint_as_float(u);
}
__device__ __forceinline__ uint32_t smem_u32(const void* p) {
    return (uint32_t)__cvta_generic_to_shared(p);
}

// tf32 tensor-core mma (sm_80+ PTX, compiles at compute_100)
__device__ __forceinline__ void mma16n8k8(float c[4], const uint32_t a[4],
                                          uint32_t b0, uint32_t b1) {
    asm volatile(
        "mma.sync.aligned.m16n8k8.row.col.f32.tf32.tf32.f32 "
        "{%0,%1,%2,%3}, {%4,%5,%6,%7}, {%8,%9}, {%0,%1,%2,%3};"
        : "+f"(c[0]), "+f"(c[1]), "+f"(c[2]), "+f"(c[3])
        : "r"(a[0]), "r"(a[1]), "r"(a[2]), "r"(a[3]), "r"(b0), "r"(b1));
}

// ---------------- W transpose (+ tf32 rounding) ----------------
__global__ __launch_bounds__(256) void k_transW(const float* __restrict__ Wf,
                                                const float* __restrict__ Wf2)
{
    __shared__ float tile[32][33];
    const int k0 = blockIdx.x * 32;     // 26
    const int n0 = blockIdx.y * 32;     // 64
    const int tx = threadIdx.x & 31, ty = threadIdx.x >> 5;   // 32 x 8
    const float* W; int ldw, nloc;
    if (n0 < 1536) { W = Wf;  ldw = 1536; nloc = n0; }
    else           { W = Wf2; ldw = 512;  nloc = n0 - 1536; }
#pragma unroll
    for (int i = 0; i < 32; i += 8)
        tile[ty + i][tx] = tf32r(W[(size_t)(k0 + ty + i) * ldw + nloc + tx]);
    __syncthreads();
#pragma unroll
    for (int i = 0; i < 32; i += 8)
        g_WT[(size_t)(n0 + ty + i) * 832 + k0 + tx] = tile[tx][ty + i];
}

// W_m^T: g_WmT[n][k] = tf32(W_fc[832+k][n])
__global__ void k_wmt(const float* __restrict__ W_fc)
{
    int n = blockIdx.x;       // 128
    int k = threadIdx.x;      // 64
    g_WmT[n * KS + k] = tf32r(W_fc[(size_t)(832 + k) * HQ + n]);
}

// ---------------- mma.sync tf32 GEMM: Z (N=1536) + scaled-G (N=512) ----------------
#define KCH 32
#define APAD 36
__global__ __launch_bounds__(256) void mma_big(
    const float* __restrict__ x, const float* __restrict__ h,
    const float* __restrict__ rbuf, const float* __restrict__ ab,
    const float* __restrict__ bias,
    float* __restrict__ Zout, float* __restrict__ Gout)
{
    extern __shared__ float sm[];           // [2][128][APAD] A + [2][128][APAD] B
    float* Ab[2] = {sm, sm + 128 * APAD};
    float* Bb[2] = {sm + 2 * 128 * APAD, sm + 3 * 128 * APAD};

    const int t = threadIdx.x;
    const int wid = t >> 5, lane = t & 31;
    const int g = lane >> 2, tg = lane & 3;
    const int warp_m = wid & 3, warp_n = wid >> 2;   // 4 x 2 warp grid
    const bool isG = blockIdx.x >= 12;
    const int n0 = blockIdx.x * 128;
    const int row0 = blockIdx.y * 128;

    const int m = t >> 1;
    const int kb = (t & 1) * 16;
    const int bidx = row0 + m;
    float alpha = 1.0f, beta = 1.0f;
    if (isG) { alpha = ab[bidx * 2]; beta = ab[bidx * 2 + 1]; }

    auto loadA16 = [&](int k0c, float4 v[4]) {
        const float* src; float sc;
        if (k0c < 256)      { src = x    + (size_t)bidx * 256 + k0c + kb;         sc = 1.0f;  }
        else if (k0c < 768) { src = h    + (size_t)bidx * 512 + (k0c - 256) + kb; sc = alpha; }
        else                { src = rbuf + (size_t)bidx * 64  + (k0c - 768) + kb; sc = beta;  }
#pragma unroll
        for (int q = 0; q < 4; q++) {
            float4 w = ((const float4*)src)[q];
            v[q] = make_float4(tf32r(w.x * sc), tf32r(w.y * sc),
                               tf32r(w.z * sc), tf32r(w.w * sc));
        }
    };
    auto stsA = [&](int buf, const float4 v[4]) {
        float* dst = Ab[buf] + m * APAD + kb;
#pragma unroll
        for (int q = 0; q < 4; q++) *(float4*)(dst + q * 4) = v[q];
    };
    auto cpB = [&](int buf, int k0c) {
        uint32_t d = smem_u32(Bb[buf] + m * APAD + kb);
        const float* s = g_WT + (size_t)(n0 + m) * 832 + k0c + kb;
#pragma unroll
        for (int q = 0; q < 4; q++)
            asm volatile("cp.async.cg.shared.global [%0], [%1], 16;"
                         :: "r"(d + q * 16), "l"(s + q * 4));
        asm volatile("cp.async.commit_group;");
    };

    float c[2][8][4];
#pragma unroll
    for (int i = 0; i < 2; i++)
#pragma unroll
        for (int j = 0; j < 8; j++)
#pragma unroll
            for (int q = 0; q < 4; q++) c[i][j][q] = 0.0f;

    {
        float4 va[4];
        loadA16(0, va);
        stsA(0, va);
        cpB(0, 0);
    }

    const int NT = 832 / KCH;   // 26
    for (int it = 0; it < NT; it++) {
        const int buf = it & 1;
        asm volatile("cp.async.wait_group 0;");
        __syncthreads();

        float4 va[4];
        if (it + 1 < NT) {
            loadA16((it + 1) * KCH, va);
            cpB(buf ^ 1, (it + 1) * KCH);
        }

        const float* Ac = Ab[buf];
        const float* Bc = Bb[buf];
#pragma unroll
        for (int kk = 0; kk < 4; kk++) {
            const int kc = kk * 8;
            uint32_t af[2][4];
#pragma unroll
            for (int i = 0; i < 2; i++) {
                const int rb = warp_m * 32 + i * 16;
                af[i][0] = __float_as_uint(Ac[(rb + g) * APAD + kc + tg]);
                af[i][1] = __float_as_uint(Ac[(rb + g + 8) * APAD + kc + tg]);
                af[i][2] = __float_as_uint(Ac[(rb + g) * APAD + kc + tg + 4]);
                af[i][3] = __float_as_uint(Ac[(rb + g + 8) * APAD + kc + tg + 4]);
            }
#pragma unroll
            for (int j = 0; j < 8; j++) {
                const int nb = warp_n * 64 + j * 8 + g;
                uint32_t b0 = __float_as_uint(Bc[nb * APAD + kc + tg]);
                uint32_t b1 = __float_as_uint(Bc[nb * APAD + kc + tg + 4]);
                mma16n8k8(c[0][j], af[0], b0, b1);
                mma16n8k8(c[1][j], af[1], b0, b1);
            }
        }

        if (it + 1 < NT) {
            __syncthreads();
            stsA(buf ^ 1, va);
        }
    }

#pragma unroll
    for (int i = 0; i < 2; i++) {
        const int r0a = row0 + warp_m * 32 + i * 16 + g;
#pragma unroll
        for (int j = 0; j < 8; j++) {
            const int cl = warp_n * 64 + j * 8 + 2 * tg;
            if (!isG) {
                const int gcol = n0 + cl;
                float bz0 = bias[gcol], bz1 = bias[gcol + 1];
                *(float2*)(Zout + (size_t)r0a * 1536 + gcol) =
                    make_float2(c[i][j][0] + bz0, c[i][j][1] + bz1);
                *(float2*)(Zout + (size_t)(r0a + 8) * 1536 + gcol) =
                    make_float2(c[i][j][2] + bz0, c[i][j][3] + bz1);
            } else {
                const int gcol = (n0 - 1536) + cl;
                *(float2*)(Gout + (size_t)r0a * 512 + gcol) =
                    make_float2(c[i][j][0], c[i][j][1]);
                *(float2*)(Gout + (size_t)(r0a + 8) * 512 + gcol) =
                    make_float2(c[i][j][2], c[i][j][3]);
            }
        }
    }
}

// ---------------- split-K base GEMM ----------------
__global__ __launch_bounds__(256, 2) void gemm_base(const float* __restrict__ W_fc)
{
    __shared__ float As[2][8][128];
    __shared__ float Bs[2][8][128];
    const int tid = threadIdx.x;
    const int tx = tid & 15, ty = tid >> 4;
    const int s = blockIdx.x;                 // 0..6
    const int row0 = blockIdx.y * 128;
    const int cs = (s < 6) ? s * 128 : 896;
    const int arow = tid >> 1, acol = (tid & 1) * 4;
    const int brow = tid >> 5, bcol = (tid & 31) * 4;

    const float* Aptr = g_xcu + (size_t)(row0 + arow) * 1024 + cs + acol;
    const float* Bptr = W_fc + (size_t)(cs + brow) * HQ + bcol;
    float* C = g_bp + (size_t)s * (BSZ * HQ);

    float acc[8][8];
#pragma unroll
    for (int i = 0; i < 8; i++)
#pragma unroll
        for (int j = 0; j < 8; j++) acc[i][j] = 0.0f;

    float4 ra = *(const float4*)Aptr;
    float4 rb = *(const float4*)Bptr;
    As[0][acol + 0][arow] = ra.x; As[0][acol + 1][arow] = ra.y;
    As[0][acol + 2][arow] = ra.z; As[0][acol + 3][arow] = ra.w;
    *(float4*)&Bs[0][brow][bcol] = rb;
    __syncthreads();

    const int nt = 128 / 8;   // 16
    for (int i = 0; i < nt; i++) {
        int cur = i & 1;
        if (i + 1 < nt) {
            ra = *(const float4*)(Aptr + (i + 1) * 8);
            rb = *(const float4*)(Bptr + (size_t)(i + 1) * 8 * HQ);
        }
#pragma unroll
        for (int kk = 0; kk < 8; kk++) {
            float4 a0 = *(const float4*)&As[cur][kk][ty * 8];
            float4 a1 = *(const float4*)&As[cur][kk][ty * 8 + 4];
            float4 b0 = *(const float4*)&Bs[cur][kk][tx * 8];
            float4 b1 = *(const float4*)&Bs[cur][kk][tx * 8 + 4];
            float av[8] = {a0.x, a0.y, a0.z, a0.w, a1.x, a1.y, a1.z, a1.w};
            float bv[8] = {b0.x, b0.y, b0.z, b0.w, b1.x, b1.y, b1.z, b1.w};
#pragma unroll
            for (int ii = 0; ii < 8; ii++)
#pragma unroll
                for (int jj = 0; jj < 8; jj++) acc[ii][jj] += av[ii] * bv[jj];
        }
        if (i + 1 < nt) {
            int nxt = cur ^ 1;
            As[nxt][acol + 0][arow] = ra.x; As[nxt][acol + 1][arow] = ra.y;
            As[nxt][acol + 2][arow] = ra.z; As[nxt][acol + 3][arow] = ra.w;
            *(float4*)&Bs[nxt][brow][bcol] = rb;
            __syncthreads();
        }
    }

#pragma unroll
    for (int i = 0; i < 8; i++) {
        float* crow = C + (size_t)(row0 + ty * 8 + i) * HQ + tx * 8;
        *(float4*)crow = make_float4(acc[i][0], acc[i][1], acc[i][2], acc[i][3]);
        *(float4*)(crow + 4) = make_float4(acc[i][4], acc[i][5], acc[i][6], acc[i][7]);
    }
}

__global__ void k_base_reduce(const float* __restrict__ b_fc)
{
    int i = blockIdx.x * 256 + threadIdx.x;
    float a = b_fc[i & 127];
#pragma unroll
    for (int s = 0; s < 7; s++) a += g_bp[(size_t)s * (BSZ * HQ) + i];
    g_base[i] = a;
}

// ---------------- fused head (tensor-core) + selection + alpha/beta ----------------
// hid = hmem[b] @ W_m via mma.sync tf32 (exact hm kept in smem for r).
struct HSmem {
    float hm[128][68];     // exact hmem rows; stride 68 -> conflict-free frags
    float wb[128][68];     // WmT tf32 (cols 0..63 used)
    float part[128][4];    // head partials per warp_n
    float red[256];
    float ri[128];
    float rs[64];
};

__global__ __launch_bounds__(256, 2) void k_headsel(
    const float* __restrict__ x, const float* __restrict__ h,
    const float* __restrict__ hmem, const float* __restrict__ prev,
    const float* __restrict__ noise_sm, const float* __restrict__ noise_sig,
    const float* __restrict__ vec_a,
    const float* __restrict__ W_full1, const float* __restrict__ bias1,
    float* __restrict__ out)
{
    extern __shared__ char smem_raw[];
    HSmem& S = *(HSmem*)smem_raw;
    const int b = blockIdx.x;
    const int t = threadIdx.x;
    const int wid = t >> 5, lane = t & 31;
    const int g = lane >> 2, tg = lane & 3;
    const int warp_m = wid & 3, warp_n = wid >> 2;

    // load hmem[b] (exact) and WmT (tf32) into smem
    {
        const float4* src = (const float4*)(hmem + (size_t)b * (MS * RS));
        const float4* wsrc = (const float4*)g_WmT;
#pragma unroll
        for (int i = 0; i < 8; i++) {
            int idx = t + i * 256;            // 0..2047
            int m = idx >> 4;
            int c4 = (idx & 15) * 4;
            *(float4*)&S.hm[m][c4] = src[idx];
            *(float4*)&S.wb[m][c4] = wsrc[idx];
        }
    }
    __syncthreads();

    // GEMM: hid[128 m][128 kq] = hm(128x64) @ WmT^T ; warp tile 32x64
    float c[2][8][4];
#pragma unroll
    for (int i = 0; i < 2; i++)
#pragma unroll
        for (int j = 0; j < 8; j++)
#pragma unroll
            for (int q = 0; q < 4; q++) c[i][j][q] = 0.0f;

#pragma unroll
    for (int kk = 0; kk < 8; kk++) {
        const int kc = kk * 8;
        uint32_t af[2][4];
#pragma unroll
        for (int i = 0; i < 2; i++) {
            const int rb = warp_m * 32 + i * 16;
            af[i][0] = __float_as_uint(tf32r(S.hm[rb + g][kc + tg]));
            af[i][1] = __float_as_uint(tf32r(S.hm[rb + g + 8][kc + tg]));
            af[i][2] = __float_as_uint(tf32r(S.hm[rb + g][kc + tg + 4]));
            af[i][3] = __float_as_uint(tf32r(S.hm[rb + g + 8][kc + tg + 4]));
        }
#pragma unroll
        for (int j = 0; j < 8; j++) {
            const int nb = warp_n * 64 + j * 8 + g;
            uint32_t b0 = __float_as_uint(S.wb[nb][kc + tg]);
            uint32_t b1 = __float_as_uint(S.wb[nb][kc + tg + 4]);
            mma16n8k8(c[0][j], af[0], b0, b1);
            mma16n8k8(c[1][j], af[1], b0, b1);
        }
    }

    // epilogue: tanh(hid + base + kWk) * vec_a, reduce over kq
    {
        float bse[8][2], va[8][2];
#pragma unroll
        for (int j = 0; j < 8; j++) {
            const int col = warp_n * 64 + j * 8 + 2 * tg;
            float2 bb = *(const float2*)(g_base + (size_t)b * HQ + col);
            float2 vv = *(const float2*)(vec_a + col);
            bse[j][0] = bb.x; bse[j][1] = bb.y;
            va[j][0] = vv.x;  va[j][1] = vv.y;
        }
#pragma unroll
        for (int i = 0; i < 2; i++) {
            const int r_lo = warp_m * 32 + i * 16 + g;
            const int r_hi = r_lo + 8;
            float p_lo = 0.0f, p_hi = 0.0f;
#pragma unroll
            for (int j = 0; j < 8; j++) {
                const int col = warp_n * 64 + j * 8 + 2 * tg;
                float2 klo = *(const float2*)(g_kWk + (size_t)r_lo * HQ + col);
                float2 khi = *(const float2*)(g_kWk + (size_t)r_hi * HQ + col);
                p_lo += tanhf(c[i][j][0] + bse[j][0] + klo.x) * va[j][0]
                      + tanhf(c[i][j][1] + bse[j][1] + klo.y) * va[j][1];
                p_hi += tanhf(c[i][j][2] + bse[j][0] + khi.x) * va[j][0]
                      + tanhf(c[i][j][3] + bse[j][1] + khi.y) * va[j][1];
            }
            p_lo += __shfl_xor_sync(0xffffffffu, p_lo, 1);
            p_lo += __shfl_xor_sync(0xffffffffu, p_lo, 2);
            p_hi += __shfl_xor_sync(0xffffffffu, p_hi, 1);
            p_hi += __shfl_xor_sync(0xffffffffu, p_hi, 2);
            if (tg == 0) {
                S.part[r_lo][warp_n] = p_lo;
                S.part[r_hi][warp_n] = p_hi;
            }
        }
    }
    __syncthreads();

    float hv = 0.0f;
    if (t < MS) {
        hv = S.part[t][0] + S.part[t][1];
        hv -= prev[(size_t)b * MS + t] * 100.0f;
    }
    // l2 normalize
    {
        float v = (t < MS) ? hv * hv : 0.0f;
        S.red[t] = v; __syncthreads();
        for (int s = 128; s > 0; s >>= 1) {
            if (t < s) S.red[t] += S.red[t + s];
            __syncthreads();
        }
        float nrm = fmaxf(sqrtf(S.red[0]), 1e-12f);
        __syncthreads();
        if (t < MS) hv /= nrm;
    }
    float z = (t < MS) ? hv + gumbelf(noise_sm[(size_t)b * MS + t]) : -INFINITY;
    float y = 0.0f;
    {
        S.red[t] = z; __syncthreads();
        for (int s = 128; s > 0; s >>= 1) {
            if (t < s) S.red[t] = fmaxf(S.red[t], S.red[t + s]);
            __syncthreads();
        }
        float zmax = S.red[0]; __syncthreads();
        float e = (t < MS) ? expf(z - zmax) : 0.0f;
        S.red[t] = e; __syncthreads();
        for (int s = 128; s > 0; s >>= 1) {
            if (t < s) S.red[t] += S.red[t + s];
            __syncthreads();
        }
        float es = S.red[0]; __syncthreads();
        y = e / es;
        S.red[t] = (t < MS) ? y : 0.0f; __syncthreads();
        for (int s = 128; s > 0; s >>= 1) {
            if (t < s) S.red[t] = fmaxf(S.red[t], S.red[t + s]);
            __syncthreads();
        }
        float ymax = S.red[0]; __syncthreads();
        if (t < MS) {
            float hard = (y == ymax) ? 1.0f : 0.0f;
            float ri = (hard - y) + y;      // exactly 0 off-support
            S.ri[t] = ri;
            g_ri[(size_t)b * MS + t] = ri;
        }
    }
    __syncthreads();

    if (t < RS) {
        float a = 0.0f;
#pragma unroll 8
        for (int m = 0; m < MS; m++) a += S.ri[m] * S.hm[m][t];
        S.rs[t] = a;
        g_r[(size_t)b * RS + t] = a;
        out[(size_t)b * 576 + HS + t] = a;
    }
    __syncthreads();

    {
        float s0 = 0.0f, s1 = 0.0f;
        for (int cI = t; cI < 832; cI += 256) {
            float v;
            if (cI < 256)      v = x[(size_t)b * XS + cI];
            else if (cI < 768) v = h[(size_t)b * HS + (cI - 256)];
            else               v = S.rs[cI - 768];
            s0 += v * W_full1[cI * 2 + 0];
            s1 += v * W_full1[cI * 2 + 1];
        }
        S.red[t] = s0; __syncthreads();
        for (int s = 128; s > 0; s >>= 1) {
            if (t < s) S.red[t] += S.red[t + s];
            __syncthreads();
        }
        float S0 = S.red[0]; __syncthreads();
        S.red[t] = s1; __syncthreads();
        for (int s = 128; s > 0; s >>= 1) {
            if (t < s) S.red[t] += S.red[t + s];
            __syncthreads();
        }
        float S1 = S.red[0];
        if (t == 0)
            g_ab[b * 2 + 0] = sigm((S0 + bias1[0] + gumbelf(noise_sig[b * 2 + 0])) * (10.0f / 3.0f));
        if (t == 1)
            g_ab[b * 2 + 1] = sigm((S1 + bias1[1] + gumbelf(noise_sig[b * 2 + 1])) * (10.0f / 3.0f));
    }
}

// ---------------- small kernels ----------------
__global__ void k_prep(const float* __restrict__ x, const float* __restrict__ c,
                       const float* __restrict__ u)
{
    __shared__ float red[128];
    int b = blockIdx.x, t = threadIdx.x;
    float uv = u[b * MS + t];
    red[t] = uv * uv; __syncthreads();
    for (int s = 64; s > 0; s >>= 1) {
        if (t < s) red[t] += red[t + s];
        __syncthreads();
    }
    float denom = fmaxf(sqrtf(red[0]), 1e-12f);
    float* row = g_xcu + (size_t)b * 1024;
    for (int i = t; i < XS; i += 128) row[i] = x[(size_t)b * XS + i];
    for (int i = t; i < HS; i += 128) row[XS + i] = c[(size_t)b * HS + i];
    row[896 + t] = uv / denom;
}

__global__ void k_kwk(const float* __restrict__ keys, const float* __restrict__ W_fc)
{
    int m = blockIdx.x, t = threadIdx.x;
    float a = 0.0f;
#pragma unroll 8
    for (int r = 0; r < KS; r++)
        a += keys[m * KS + r] * W_fc[(768 + r) * HQ + t];
    g_kWk[m * HQ + t] = a;
}

__global__ void k_epi(const float* __restrict__ c, const float* __restrict__ bias2,
                      float* __restrict__ out)
{
    int b = blockIdx.x, t = threadIdx.x;   // 256 threads
    for (int j = t; j < HS; j += 256) {
        size_t bj = (size_t)b * HS + j;
        float pre = g_G[bj] + bias2[j];
        float nc0 = tanhf(pre);
        float zi = g_Z[(size_t)b * 1536 + j];
        float zf = g_Z[(size_t)b * 1536 + 512 + j];
        float zo = g_Z[(size_t)b * 1536 + 1024 + j];
        float cc = c[bj];
        float ncv = cc * sigm(zf + 1.0f) + sigm(zi) * nc0;
        float nh = tanhf(ncv) * sigm(zo);
        out[(size_t)b * 576 + j] = nh;
        g_nh[bj] = nh;
    }
}

__global__ __launch_bounds__(256) void k_hw(
    const float* __restrict__ x, const float* __restrict__ W_fc1,
    const float* __restrict__ b_fc1)
{
    __shared__ float Ws[64][64];
    __shared__ float Asb[16][68];
    const int b0 = blockIdx.x * 16;
    const int t = threadIdx.x;
    const int n = t & 63, bl = t >> 6;
    float acc[4] = {0.0f, 0.0f, 0.0f, 0.0f};

    for (int k0 = 0; k0 < 768; k0 += 64) {
#pragma unroll
        for (int i = 0; i < 4; i++) {
            int idx = t + i * 256;
            int row = idx >> 4, c4 = (idx & 15) * 4;
            *(float4*)&Ws[row][c4] = *(const float4*)(W_fc1 + (size_t)(k0 + row) * RS + c4);
        }
        {
            int idx = t;
            int row = idx >> 4, c4 = (idx & 15) * 4;
            int gb = b0 + row, gk = k0 + c4;
            float4 v;
            if (gk < 256) v = *(const float4*)(x + (size_t)gb * XS + gk);
            else          v = *(const float4*)(g_nh + (size_t)gb * HS + (gk - 256));
            *(float4*)&Asb[row][c4] = v;
        }
        __syncthreads();
#pragma unroll 16
        for (int kk = 0; kk < 64; kk++) {
            float w = Ws[kk][n];
#pragma unroll
            for (int i = 0; i < 4; i++) acc[i] += Asb[bl * 4 + i][kk] * w;
        }
        __syncthreads();
    }
    float bb = b_fc1[n];
#pragma unroll
    for (int i = 0; i < 4; i++)
        g_hw[(size_t)(b0 + bl * 4 + i) * RS + n] = acc[i] + bb;
}

__global__ void k_hmem_copy(const float* __restrict__ hmem, float* __restrict__ out)
{
    size_t idx = (size_t)blockIdx.x * 256 + threadIdx.x;
    ((float4*)out)[(size_t)(BSZ * 576 / 4) + idx] = ((const float4*)hmem)[idx];
}

__global__ void k_hmem_fix(const float* __restrict__ hmem, float* __restrict__ out)
{
    __shared__ float w[128];
    const int b = blockIdx.x, t = threadIdx.x;
    w[t] = g_ri[(size_t)b * MS + t];
    __syncthreads();
    for (int m = 0; m < MS; m++) {
        float wm = w[m];
        if (wm != 0.0f && t < RS) {
            float hv = hmem[((size_t)b * MS + m) * RS + t];
            float hwv = g_hw[(size_t)b * RS + t];
            out[(size_t)BSZ * 576 + ((size_t)b * MS + m) * RS + t] =
                hwv * wm + hv * (1.0f - wm);
        }
    }
}

// ---------------- launch ----------------
extern "C" void kernel_launch(void* const* d_in, const int* in_sizes, int n_in,
                              void* d_out, int out_size)
{
    const float* x        = (const float*)d_in[0];
    const float* h        = (const float*)d_in[1];
    const float* c        = (const float*)d_in[2];
    const float* hmem     = (const float*)d_in[3];
    const float* u_t      = (const float*)d_in[4];
    const float* prev     = (const float*)d_in[5];
    const float* W_full   = (const float*)d_in[6];
    const float* bias     = (const float*)d_in[7];
    const float* W_full1  = (const float*)d_in[8];
    const float* bias1    = (const float*)d_in[9];
    const float* W_full2  = (const float*)d_in[10];
    const float* bias2    = (const float*)d_in[11];
    const float* keys     = (const float*)d_in[12];
    const float* vec_a    = (const float*)d_in[13];
    const float* W_fc     = (const float*)d_in[14];
    const float* b_fc     = (const float*)d_in[15];
    const float* W_fc1    = (const float*)d_in[16];
    const float* b_fc1    = (const float*)d_in[17];
    const float* noise_sm = (const float*)d_in[18];
    const float* noise_sig= (const float*)d_in[19];
    float* out = (float*)d_out;

    float *p_r, *p_ab, *p_Z, *p_G;
    cudaGetSymbolAddress((void**)&p_r,  g_r);
    cudaGetSymbolAddress((void**)&p_ab, g_ab);
    cudaGetSymbolAddress((void**)&p_Z,  g_Z);
    cudaGetSymbolAddress((void**)&p_G,  g_G);

    const int MMASMEM = 4 * 128 * APAD * 4;   // 73728 B

    static cudaStream_t s2 = nullptr, s3 = nullptr;
    static cudaEvent_t e1 = nullptr, e2 = nullptr, e3 = nullptr;
    static bool init_done = false;
    if (!init_done) {
        cudaFuncSetAttribute(k_headsel, cudaFuncAttributeMaxDynamicSharedMemorySize,
                             (int)sizeof(HSmem));
        cudaFuncSetAttribute(mma_big, cudaFuncAttributeMaxDynamicSharedMemorySize, MMASMEM);
        cudaStreamCreateWithFlags(&s2, cudaStreamNonBlocking);
        cudaStreamCreateWithFlags(&s3, cudaStreamNonBlocking);
        cudaEventCreateWithFlags(&e1, cudaEventDisableTiming);
        cudaEventCreateWithFlags(&e2, cudaEventDisableTiming);
        cudaEventCreateWithFlags(&e3, cudaEventDisableTiming);
        init_done = true;
    }

    // fork: bulk hmem copy on s2; W transpose (needed only by mma_big) on s3
    cudaEventRecord(e1, 0);
    cudaStreamWaitEvent(s2, e1, 0);
    cudaStreamWaitEvent(s3, e1, 0);
    k_hmem_copy<<<(BSZ * MS * 16) / 256, 256, 0, s2>>>(hmem, out);
    cudaEventRecord(e2, s2);
    k_transW<<<dim3(26, 64), 256, 0, s3>>>(W_full, W_full2);
    cudaEventRecord(e3, s3);

    // main chain
    k_prep<<<BSZ, 128>>>(x, c, u_t);
    k_kwk<<<MS, HQ>>>(keys, W_fc);
    k_wmt<<<MS, KS>>>(W_fc);

    gemm_base<<<dim3(7, 16), 256>>>(W_fc);
    k_base_reduce<<<BSZ * HQ / 256, 256>>>(b_fc);

    k_headsel<<<BSZ, 256, sizeof(HSmem)>>>(x, h, hmem, prev, noise_sm, noise_sig,
                                           vec_a, W_full1, bias1, out);

    cudaStreamWaitEvent(0, e3, 0);
    mma_big<<<dim3(16, 16), 256, MMASMEM>>>(x, h, p_r, p_ab, bias, p_Z, p_G);

    k_epi<<<BSZ, 256>>>(c, bias2, out);
    k_hw<<<BSZ / 16, 256>>>(x, W_fc1, b_fc1);

    cudaStreamWaitEvent(0, e2, 0);
    k_hmem_fix<<<BSZ, 128>>>(hmem, out);
}